// round 8
// baseline (speedup 1.0000x reference)
#include <cuda_runtime.h>
#include <cuda_fp16.h>
#include <math.h>
#include <cstdint>

#define HW      96
#define NPIX    9216
#define NCH     21
#define RAD     35
#define KW      71
#define KSPLIT  2
#define KHALF   4608
#define CHUNK   128           // k per pipeline chunk
#define NCHUNK  36            // KHALF / CHUNK
#define NSTAGE  6
#define A_STRIDE 144          // padded u8 row stride (conflict-free LDS)
#define A_PANEL (128 * A_STRIDE)   // 18432
#define B_PANEL 4096               // 32 ch * 128B (64 k fp16, swizzled)
#define STAGE_BYTES (A_PANEL + 2 * B_PANEL)  // 26624
#define MTILES  72
#define GEMM_SMEM (NSTAGE * STAGE_BYTES + 1024)
#define STRIPS  12
#define SROWS   8
#define HALO    78            // 8 + 2*35
#define TROW    (HW + 2 * RAD) // 166
#define BSCALE  (4.0f / 255.0f)

// ---------------- device scratch ----------------
__device__ unsigned char g_Ku[(size_t)NPIX * NPIX];  // 85 MB u8 kernel matrix
__device__ float  g_feat[5][NPIX];
__device__ float  g_rowpart[NPIX * MTILES];
__device__ float  g_rowinv[NPIX];
__device__ float  g_U[NCH * NPIX];
__device__ float  g_q[NCH * NPIX];
__device__ __half g_qh[32 * NPIX];
__device__ float  g_part[KSPLIT * NCH * NPIX];
__device__ float  g_qsf[NCH * NPIX];
__device__ float  g_g1d[KW];

// ---------------- PTX helpers ----------------
__device__ __forceinline__ uint32_t s2u(const void* p) {
    uint32_t a;
    asm("{ .reg .u64 t; cvta.to.shared.u64 t, %1; cvt.u32.u64 %0, t; }" : "=r"(a) : "l"(p));
    return a;
}
#define SWZ(b) ((b) ^ (((b) >> 3) & 0x70))
#define CP16(dst, src) \
    asm volatile("cp.async.cg.shared.global [%0], [%1], 16;" :: "r"(dst), "l"(src) : "memory")
#define CP_COMMIT() asm volatile("cp.async.commit_group;" ::: "memory")
#define CP_WAIT(n)  asm volatile("cp.async.wait_group %0;" :: "n"(n) : "memory")
#define LDSU16(r, addr) \
    asm volatile("ld.shared.u16 %0, [%1];" : "=r"(r) : "r"(addr))
#define LDSM4(r0, r1, r2, r3, addr) \
    asm volatile("ldmatrix.sync.aligned.m8n8.x4.shared.b16 {%0,%1,%2,%3}, [%4];" \
                 : "=r"(r0), "=r"(r1), "=r"(r2), "=r"(r3) : "r"(addr))
#define LDSM2(r0, r1, addr) \
    asm volatile("ldmatrix.sync.aligned.m8n8.x2.shared.b16 {%0,%1}, [%2];" \
                 : "=r"(r0), "=r"(r1) : "r"(addr))
#define MMA16816(d, a0, a1, a2, a3, b0, b1) \
    asm volatile("mma.sync.aligned.m16n8k16.row.col.f32.f16.f16.f32 " \
                 "{%0,%1,%2,%3}, {%4,%5,%6,%7}, {%8,%9}, {%0,%1,%2,%3};" \
                 : "+f"((d)[0]), "+f"((d)[1]), "+f"((d)[2]), "+f"((d)[3]) \
                 : "r"(a0), "r"(a1), "r"(a2), "r"(a3), "r"(b0), "r"(b1))

// two u8 (low 2 bytes of w) -> packed fp16x2 with exact integer values 0..255
__device__ __forceinline__ uint32_t u8x2_to_h2(uint32_t w) {
    uint32_t r;
    asm("prmt.b32 %0, %1, 0, 0x4140;" : "=r"(r) : "r"(w));   // {0,b1,0,b0}
    r |= 0x64006400u;                                        // 1024+b (exact)
    asm("sub.rn.f16x2 %0, %0, %1;" : "+r"(r) : "r"(0x64006400u));
    return r;                                                // {b1, b0} exact
}

// ---------------- setup ----------------
__global__ void k_feat(const float* __restrict__ ref, const float* __restrict__ kstd) {
    if (blockIdx.x == 0 && threadIdx.x == 0) {
        float w[KW]; float s = 0.f;
        for (int t = 0; t < KW; ++t) {
            float d = (float)t - (float)RAD;
            w[t] = expf(-(d * d) / 72.0f); s += w[t];
        }
        float inv = 1.0f / s;
        for (int t = 0; t < KW; ++t) g_g1d[t] = w[t] * inv;
    }
    int i = blockIdx.x * blockDim.x + threadIdx.x;
    if (i >= NPIX) return;
    int y = i / HW, x = i % HW;
    g_feat[0][i] = (float)y / kstd[0];
    g_feat[1][i] = (float)x / kstd[1];
    g_feat[2][i] = ref[0 * NPIX + i] / kstd[2];
    g_feat[3][i] = ref[1 * NPIX + i] / kstd[3];
    g_feat[4][i] = ref[2 * NPIX + i] / kstd[4];
}

__global__ void __launch_bounds__(256) k_K() {
    __shared__ float s_fr[5][32];
    __shared__ float s_fc[5][128];
    const int rowBase = blockIdx.y * 32;
    const int colBase = blockIdx.x * 128;
    const int tid = threadIdx.x;

    if (tid < 5 * 32) { int d = tid / 32, rr = tid % 32; s_fr[d][rr] = g_feat[d][rowBase + rr]; }
    for (int idx = tid; idx < 5 * 128; idx += 256) {
        int d = idx / 128, cc = idx % 128;
        s_fc[d][cc] = g_feat[d][colBase + cc];
    }
    __syncthreads();

    const int r = tid >> 5;
    const int cl = tid & 31;

    float fr[4][5], fc[4][5];
#pragma unroll
    for (int a = 0; a < 4; ++a)
#pragma unroll
        for (int d = 0; d < 5; ++d) fr[a][d] = s_fr[d][r * 4 + a];
#pragma unroll
    for (int b = 0; b < 4; ++b)
#pragma unroll
        for (int d = 0; d < 5; ++d) fc[b][d] = s_fc[d][cl + 32 * b];

#pragma unroll
    for (int a = 0; a < 4; ++a) {
        const int row = rowBase + r * 4 + a;
        const size_t rowOff = (size_t)row * NPIX;
        float rs = 0.f;
#pragma unroll
        for (int b = 0; b < 4; ++b) {
            float d2 = 0.f;
#pragma unroll
            for (int d = 0; d < 5; ++d) {
                float df = fr[a][d] - fc[b][d];
                d2 = fmaf(df, df, d2);
            }
            float v = __expf(-0.5f * d2);
            rs += v;
            g_Ku[rowOff + colBase + cl + 32 * b] =
                (unsigned char)__float2uint_rn(v * 255.0f);
        }
#pragma unroll
        for (int o = 16; o; o >>= 1) rs += __shfl_xor_sync(0xffffffffu, rs, o);
        if (cl == 0) g_rowpart[row * MTILES + blockIdx.x] = rs;
    }
}

__global__ void k_init(const float* __restrict__ unary) {
    int i = blockIdx.x * blockDim.x + threadIdx.x;
    if (i >= NPIX) return;
    float s = 0.f;
    const float* p = g_rowpart + i * MTILES;
#pragma unroll
    for (int b = 0; b < MTILES; ++b) s += p[b];
    float ri = 1.0f / (sqrtf(s) + 1e-8f);
    g_rowinv[i] = ri;

    float L[NCH];
    float m = -1e30f;
#pragma unroll
    for (int c = 0; c < NCH; ++c) {
        float u = unary[c * NPIX + i];
        u = fminf(fmaxf(u, 1e-5f), 1.0f);
        float lu = logf(u);
        g_U[c * NPIX + i] = lu;
        L[c] = lu;
        m = fmaxf(m, lu);
    }
    float se = 0.f;
#pragma unroll
    for (int c = 0; c < NCH; ++c) { L[c] = __expf(L[c] - m); se += L[c]; }
    float inv = 1.0f / se;
#pragma unroll
    for (int c = 0; c < NCH; ++c) {
        float q = L[c] * inv;
        g_q[c * NPIX + i] = q;
        g_qh[c * NPIX + i] = __float2half_rn(q * ri);
    }
#pragma unroll
    for (int c = NCH; c < 32; ++c) g_qh[c * NPIX + i] = __float2half_rn(0.f);
}

// ---------------- strip-parallel separable conv ----------------
__global__ void __launch_bounds__(384) k_conv() {
    __shared__ float sImg[HALO * HW];
    __shared__ float sTmp[SROWS * TROW];
    __shared__ float sW[KW];
    const int c = blockIdx.x / STRIPS;
    const int strip = blockIdx.x % STRIPS;
    const int y0 = strip * SROWS;
    const int rowLo = y0 - RAD;
    const int tid = threadIdx.x;

    if (tid < KW) sW[tid] = g_g1d[tid];
    const float* src = g_q + c * NPIX;
    for (int p = tid; p < HALO * HW; p += 384) {
        int r = p / HW, x = p - r * HW;
        int gr = rowLo + r;
        sImg[p] = (gr >= 0 && gr < HW) ? src[gr * HW + x] : 0.f;
    }
    for (int p = tid; p < SROWS * TROW; p += 384) sTmp[p] = 0.f;
    __syncthreads();

    for (int p = tid; p < SROWS * HW; p += 384) {
        int yy = p / HW, x = p - yy * HW;
        const float* col = sImg + yy * HW + x;
        float s0 = 0.f, s1 = 0.f, s2 = 0.f, s3 = 0.f;
#pragma unroll
        for (int t = 0; t < 68; t += 4) {
            s0 = fmaf(sW[t],     col[t * HW],       s0);
            s1 = fmaf(sW[t + 1], col[(t + 1) * HW], s1);
            s2 = fmaf(sW[t + 2], col[(t + 2) * HW], s2);
            s3 = fmaf(sW[t + 3], col[(t + 3) * HW], s3);
        }
        s0 = fmaf(sW[68], col[68 * HW], s0);
        s1 = fmaf(sW[69], col[69 * HW], s1);
        s2 = fmaf(sW[70], col[70 * HW], s2);
        sTmp[yy * TROW + RAD + x] = (s0 + s1) + (s2 + s3);
    }
    __syncthreads();

    float* dst = g_qsf + c * NPIX + y0 * HW;
    for (int p = tid; p < SROWS * HW; p += 384) {
        int yy = p / HW, x = p - yy * HW;
        const float* row = sTmp + yy * TROW + x;
        float s0 = 0.f, s1 = 0.f, s2 = 0.f, s3 = 0.f;
#pragma unroll
        for (int t = 0; t < 68; t += 4) {
            s0 = fmaf(sW[t],     row[t],     s0);
            s1 = fmaf(sW[t + 1], row[t + 1], s1);
            s2 = fmaf(sW[t + 2], row[t + 2], s2);
            s3 = fmaf(sW[t + 3], row[t + 3], s3);
        }
        s0 = fmaf(sW[68], row[68], s0);
        s1 = fmaf(sW[69], row[69], s1);
        s2 = fmaf(sW[70], row[70], s2);
        dst[p] = (s0 + s1) + (s2 + s3);
    }
}

// ---------------- u8-A HMMA split-K GEMM ----------------
// A: u8 K-matrix rows (unswizzled, 144B stride), converted to exact-int fp16
// in registers. B: fp16 qn, swizzled + ldmatrix (as before).
__global__ void __launch_bounds__(256, 1) k_gemm_mma() {
    extern __shared__ char dynRaw[];
    const uint32_t dynb = (s2u(dynRaw) + 1023u) & ~1023u;
    const int tid = threadIdx.x, w = tid >> 5, lid = tid & 31;
    const int m0 = blockIdx.x * 128;
    const int zbase = blockIdx.y * KHALF;

    const unsigned char* Abase = g_Ku + (size_t)m0 * NPIX + zbase;
    const __half* Bbase = g_qh + zbase;

    auto load_chunk = [&](int ci) {
        const uint32_t stage = dynb + (uint32_t)(ci % NSTAGE) * STAGE_BYTES;
        const int koff = ci * CHUNK;
#pragma unroll
        for (int u = tid; u < 1536; u += 256) {
            uint32_t dst; const void* src;
            if (u < 1024) {                 // A: 128 rows x 128B
                int r = u >> 3, t = u & 7;
                src = Abase + (size_t)r * NPIX + koff + t * 16;
                dst = stage + (uint32_t)(r * A_STRIDE + t * 16);
            } else {                        // B: 2 panels x 32 ch x 128B
                int v = u - 1024;
                int pl = v >> 8, cc = (v >> 3) & 31, t = v & 7;
                src = Bbase + (size_t)cc * NPIX + koff + pl * 64 + t * 8;
                dst = stage + A_PANEL + (uint32_t)pl * B_PANEL
                    + SWZ((uint32_t)(cc * 128 + t * 16));
            }
            CP16(dst, src);
        }
        CP_COMMIT();
    };

    float acc[3][4];
#pragma unroll
    for (int g = 0; g < 3; ++g)
#pragma unroll
        for (int k = 0; k < 4; ++k) acc[g][k] = 0.f;

    for (int i = 0; i < NSTAGE - 1; ++i) load_chunk(i);

    // per-thread A fragment base: row = w*16 + lid/4, byte col = (lid%4)*2
    const uint32_t aBase0 = (uint32_t)((w * 16 + (lid >> 2)) * A_STRIDE + (lid & 3) * 2);
    const uint32_t bRowOff01 = (uint32_t)(((lid & 7) + ((lid >> 4) << 3)) * 128) + (((lid >> 3) & 1) << 4);
    const uint32_t bRowOff2 = (uint32_t)((16 + (lid & 7)) * 128) + (((lid >> 3) & 1) << 4);

    for (int i = 0; i < NCHUNK; ++i) {
        if (i + NSTAGE - 1 < NCHUNK) CP_WAIT(NSTAGE - 2); else CP_WAIT(0);
        __syncthreads();
        if (i + NSTAGE - 1 < NCHUNK) load_chunk(i + NSTAGE - 1);

        const uint32_t stage = dynb + (uint32_t)(i % NSTAGE) * STAGE_BYTES;
#pragma unroll
        for (int pl = 0; pl < 2; ++pl) {
            const uint32_t aP = stage + (uint32_t)pl * 64 + aBase0;
            const uint32_t bufB = stage + A_PANEL + (uint32_t)pl * B_PANEL;
#pragma unroll
            for (int ks = 0; ks < 4; ++ks) {
                const uint32_t ad = aP + (uint32_t)ks * 16;
                uint32_t w0, w1, w2, w3;
                LDSU16(w0, ad);
                LDSU16(w1, ad + 8 * A_STRIDE);
                LDSU16(w2, ad + 8);
                LDSU16(w3, ad + 8 * A_STRIDE + 8);
                const uint32_t a0 = u8x2_to_h2(w0);
                const uint32_t a1 = u8x2_to_h2(w1);
                const uint32_t a2 = u8x2_to_h2(w2);
                const uint32_t a3 = u8x2_to_h2(w3);

                const uint32_t kb = (uint32_t)ks * 32;
                uint32_t b00, b01, b10, b11, b20, b21;
                LDSM4(b00, b01, b10, b11, bufB + SWZ(bRowOff01 + kb));
                LDSM2(b20, b21, bufB + SWZ(bRowOff2 + kb));
                MMA16816(acc[0], a0, a1, a2, a3, b00, b01);
                MMA16816(acc[1], a0, a1, a2, a3, b10, b11);
                MMA16816(acc[2], a0, a1, a2, a3, b20, b21);
            }
        }
    }

    const int row0 = m0 + w * 16 + (lid >> 2);
    const int c0 = (lid & 3) * 2;
    float* pp = g_part + (size_t)blockIdx.y * (NCH * NPIX);
#pragma unroll
    for (int g = 0; g < 3; ++g) {
#pragma unroll
        for (int k = 0; k < 4; ++k) {
            int c = g * 8 + c0 + (k & 1);
            int row = row0 + ((k >> 1) << 3);
            if (c < NCH) pp[c * NPIX + row] = acc[g][k];
        }
    }
}

// ---------------- softmax update ----------------
__global__ void k_update(float* __restrict__ out, int final_it) {
    int i = blockIdx.x * blockDim.x + threadIdx.x;
    if (i >= NPIX) return;
    float ri = g_rowinv[i];
    float* dst = final_it ? out : g_q;

    float L[NCH];
    float m = -1e30f;
#pragma unroll
    for (int c = 0; c < NCH; ++c) {
        float s = g_part[c * NPIX + i] + g_part[(NCH + c) * NPIX + i];
        float l = g_U[c * NPIX + i] + (s * ri) * BSCALE + 2.0f * g_qsf[c * NPIX + i];
        L[c] = l;
        m = fmaxf(m, l);
    }
    float se = 0.f;
#pragma unroll
    for (int c = 0; c < NCH; ++c) { L[c] = __expf(L[c] - m); se += L[c]; }
    float inv = 1.0f / se;
#pragma unroll
    for (int c = 0; c < NCH; ++c) {
        float q = L[c] * inv;
        dst[c * NPIX + i] = q;
        g_qh[c * NPIX + i] = __float2half_rn(q * ri);
    }
}

// ---------------- launch ----------------
extern "C" void kernel_launch(void* const* d_in, const int* in_sizes, int n_in,
                              void* d_out, int out_size) {
    const float* unary = nullptr;
    const float* ref = nullptr;
    const float* kstd = nullptr;
    for (int i = 0; i < n_in; ++i) {
        if (in_sizes[i] == NCH * NPIX) unary = (const float*)d_in[i];
        else if (in_sizes[i] == 3 * NPIX) ref = (const float*)d_in[i];
        else if (in_sizes[i] == 5) kstd = (const float*)d_in[i];
    }

    cudaFuncSetAttribute(k_gemm_mma, cudaFuncAttributeMaxDynamicSharedMemorySize, GEMM_SMEM);

    k_feat<<<(NPIX + 255) / 256, 256>>>(ref, kstd);
    k_K<<<dim3(NPIX / 128, NPIX / 32), 256>>>();
    k_init<<<(NPIX + 255) / 256, 256>>>(unary);

    for (int it = 0; it < 5; ++it) {
        k_conv<<<NCH * STRIPS, 384>>>();
        k_gemm_mma<<<dim3(MTILES, KSPLIT), 256, GEMM_SMEM>>>();
        k_update<<<(NPIX + 255) / 256, 256>>>((float*)d_out, it == 4 ? 1 : 0);
    }
}

// round 9
// speedup vs baseline: 1.1113x; 1.1113x over previous
#include <cuda_runtime.h>
#include <cuda_fp16.h>
#include <math.h>
#include <cstdint>

#define HW      96
#define NPIX    9216
#define NCH     21
#define RAD     35
#define KW      71
#define KSPLIT  2
#define KHALF   4608
#define CHUNK   128           // k per pipeline chunk
#define NCHUNK  36            // KHALF / CHUNK
#define NSTAGE  8
#define A_STRIDE 144          // padded u8 row stride (conflict-free LDS)
#define A_PANEL (128 * A_STRIDE)   // 18432
#define B_PANEL 4096               // 32 ch * 128B (64 k fp16, swizzled)
#define STAGE_BYTES (A_PANEL + 2 * B_PANEL)  // 26624
#define MTILES  72
#define GEMM_SMEM (NSTAGE * STAGE_BYTES + 1024)
#define STRIPS  6
#define SROWS   16
#define HALO    86            // 16 + 2*35
#define TROW    (HW + 2 * RAD) // 166
#define BSCALE  (4.0f / 255.0f)

// ---------------- device scratch ----------------
__device__ unsigned char g_Ku[(size_t)NPIX * NPIX];  // 85 MB u8 kernel matrix
__device__ float  g_feat[5][NPIX];
__device__ float  g_rowpart[NPIX * MTILES];
__device__ float  g_rowinv[NPIX];
__device__ float  g_U[NCH * NPIX];
__device__ float  g_q[NCH * NPIX];
__device__ __half g_qh[32 * NPIX];
__device__ float  g_part[KSPLIT * NCH * NPIX];
__device__ float  g_qsf[NCH * NPIX];
__device__ float  g_g1d[KW];

// ---------------- PTX helpers ----------------
__device__ __forceinline__ uint32_t s2u(const void* p) {
    uint32_t a;
    asm("{ .reg .u64 t; cvta.to.shared.u64 t, %1; cvt.u32.u64 %0, t; }" : "=r"(a) : "l"(p));
    return a;
}
#define SWZ(b) ((b) ^ (((b) >> 3) & 0x70))
#define CP16(dst, src) \
    asm volatile("cp.async.cg.shared.global [%0], [%1], 16;" :: "r"(dst), "l"(src) : "memory")
#define CP_COMMIT() asm volatile("cp.async.commit_group;" ::: "memory")
#define CP_WAIT(n)  asm volatile("cp.async.wait_group %0;" :: "n"(n) : "memory")
#define LDSU16(r, addr) \
    asm volatile("ld.shared.u16 %0, [%1];" : "=r"(r) : "r"(addr))
#define LDSM4(r0, r1, r2, r3, addr) \
    asm volatile("ldmatrix.sync.aligned.m8n8.x4.shared.b16 {%0,%1,%2,%3}, [%4];" \
                 : "=r"(r0), "=r"(r1), "=r"(r2), "=r"(r3) : "r"(addr))
#define LDSM2(r0, r1, addr) \
    asm volatile("ldmatrix.sync.aligned.m8n8.x2.shared.b16 {%0,%1}, [%2];" \
                 : "=r"(r0), "=r"(r1) : "r"(addr))
#define MMA16816(d, a0, a1, a2, a3, b0, b1) \
    asm volatile("mma.sync.aligned.m16n8k16.row.col.f32.f16.f16.f32 " \
                 "{%0,%1,%2,%3}, {%4,%5,%6,%7}, {%8,%9}, {%0,%1,%2,%3};" \
                 : "+f"((d)[0]), "+f"((d)[1]), "+f"((d)[2]), "+f"((d)[3]) \
                 : "r"(a0), "r"(a1), "r"(a2), "r"(a3), "r"(b0), "r"(b1))

// two u8 (low 2 bytes of w) -> packed fp16x2 with exact integer values 0..255
__device__ __forceinline__ uint32_t u8x2_to_h2(uint32_t w) {
    uint32_t r;
    asm("prmt.b32 %0, %1, 0, 0x4140;" : "=r"(r) : "r"(w));   // {0,b1,0,b0}
    r |= 0x64006400u;                                        // 1024+b (exact)
    asm("sub.rn.f16x2 %0, %0, %1;" : "+r"(r) : "r"(0x64006400u));
    return r;                                                // {b1, b0} exact
}

// ---------------- setup ----------------
__global__ void k_feat(const float* __restrict__ ref, const float* __restrict__ kstd) {
    if (blockIdx.x == 0 && threadIdx.x == 0) {
        float w[KW]; float s = 0.f;
        for (int t = 0; t < KW; ++t) {
            float d = (float)t - (float)RAD;
            w[t] = expf(-(d * d) / 72.0f); s += w[t];
        }
        float inv = 1.0f / s;
        for (int t = 0; t < KW; ++t) g_g1d[t] = w[t] * inv;
    }
    int i = blockIdx.x * blockDim.x + threadIdx.x;
    if (i >= NPIX) return;
    int y = i / HW, x = i % HW;
    g_feat[0][i] = (float)y / kstd[0];
    g_feat[1][i] = (float)x / kstd[1];
    g_feat[2][i] = ref[0 * NPIX + i] / kstd[2];
    g_feat[3][i] = ref[1 * NPIX + i] / kstd[3];
    g_feat[4][i] = ref[2 * NPIX + i] / kstd[4];
}

__global__ void __launch_bounds__(256) k_K() {
    __shared__ float s_fr[5][32];
    __shared__ float s_fc[5][128];
    const int rowBase = blockIdx.y * 32;
    const int colBase = blockIdx.x * 128;
    const int tid = threadIdx.x;

    if (tid < 5 * 32) { int d = tid / 32, rr = tid % 32; s_fr[d][rr] = g_feat[d][rowBase + rr]; }
    for (int idx = tid; idx < 5 * 128; idx += 256) {
        int d = idx / 128, cc = idx % 128;
        s_fc[d][cc] = g_feat[d][colBase + cc];
    }
    __syncthreads();

    const int r = tid >> 5;
    const int cl = tid & 31;

    float fr[4][5], fc[4][5];
#pragma unroll
    for (int a = 0; a < 4; ++a)
#pragma unroll
        for (int d = 0; d < 5; ++d) fr[a][d] = s_fr[d][r * 4 + a];
#pragma unroll
    for (int b = 0; b < 4; ++b)
#pragma unroll
        for (int d = 0; d < 5; ++d) fc[b][d] = s_fc[d][cl + 32 * b];

#pragma unroll
    for (int a = 0; a < 4; ++a) {
        const int row = rowBase + r * 4 + a;
        const size_t rowOff = (size_t)row * NPIX;
        float rs = 0.f;
#pragma unroll
        for (int b = 0; b < 4; ++b) {
            float d2 = 0.f;
#pragma unroll
            for (int d = 0; d < 5; ++d) {
                float df = fr[a][d] - fc[b][d];
                d2 = fmaf(df, df, d2);
            }
            float v = __expf(-0.5f * d2);
            rs += v;
            g_Ku[rowOff + colBase + cl + 32 * b] =
                (unsigned char)__float2uint_rn(v * 255.0f);
        }
#pragma unroll
        for (int o = 16; o; o >>= 1) rs += __shfl_xor_sync(0xffffffffu, rs, o);
        if (cl == 0) g_rowpart[row * MTILES + blockIdx.x] = rs;
    }
}

__global__ void k_init(const float* __restrict__ unary) {
    int i = blockIdx.x * blockDim.x + threadIdx.x;
    if (i >= NPIX) return;
    float s = 0.f;
    const float* p = g_rowpart + i * MTILES;
#pragma unroll
    for (int b = 0; b < MTILES; ++b) s += p[b];
    float ri = 1.0f / (sqrtf(s) + 1e-8f);
    g_rowinv[i] = ri;

    float L[NCH];
    float m = -1e30f;
#pragma unroll
    for (int c = 0; c < NCH; ++c) {
        float u = unary[c * NPIX + i];
        u = fminf(fmaxf(u, 1e-5f), 1.0f);
        float lu = logf(u);
        g_U[c * NPIX + i] = lu;
        L[c] = lu;
        m = fmaxf(m, lu);
    }
    float se = 0.f;
#pragma unroll
    for (int c = 0; c < NCH; ++c) { L[c] = __expf(L[c] - m); se += L[c]; }
    float inv = 1.0f / se;
#pragma unroll
    for (int c = 0; c < NCH; ++c) {
        float q = L[c] * inv;
        g_q[c * NPIX + i] = q;
        g_qh[c * NPIX + i] = __float2half_rn(q * ri);
    }
#pragma unroll
    for (int c = NCH; c < 32; ++c) g_qh[c * NPIX + i] = __float2half_rn(0.f);
}

// ---------------- strip-parallel separable conv (R7 geometry) ----------------
__global__ void __launch_bounds__(384) k_conv() {
    __shared__ float sImg[HALO * HW];
    __shared__ float sTmp[SROWS * TROW];
    __shared__ float sW[KW];
    const int c = blockIdx.x / STRIPS;
    const int strip = blockIdx.x % STRIPS;
    const int y0 = strip * SROWS;
    const int rowLo = y0 - RAD;
    const int tid = threadIdx.x;

    if (tid < KW) sW[tid] = g_g1d[tid];
    const float* src = g_q + c * NPIX;
    for (int p = tid; p < HALO * HW; p += 384) {
        int r = p / HW, x = p - r * HW;
        int gr = rowLo + r;
        sImg[p] = (gr >= 0 && gr < HW) ? src[gr * HW + x] : 0.f;
    }
    for (int p = tid; p < SROWS * TROW; p += 384) sTmp[p] = 0.f;
    __syncthreads();

    for (int p = tid; p < SROWS * HW; p += 384) {
        int yy = p / HW, x = p - yy * HW;
        const float* col = sImg + yy * HW + x;
        float s0 = 0.f, s1 = 0.f, s2 = 0.f, s3 = 0.f;
#pragma unroll
        for (int t = 0; t < 68; t += 4) {
            s0 = fmaf(sW[t],     col[t * HW],       s0);
            s1 = fmaf(sW[t + 1], col[(t + 1) * HW], s1);
            s2 = fmaf(sW[t + 2], col[(t + 2) * HW], s2);
            s3 = fmaf(sW[t + 3], col[(t + 3) * HW], s3);
        }
        s0 = fmaf(sW[68], col[68 * HW], s0);
        s1 = fmaf(sW[69], col[69 * HW], s1);
        s2 = fmaf(sW[70], col[70 * HW], s2);
        sTmp[yy * TROW + RAD + x] = (s0 + s1) + (s2 + s3);
    }
    __syncthreads();

    float* dst = g_qsf + c * NPIX + y0 * HW;
    for (int p = tid; p < SROWS * HW; p += 384) {
        int yy = p / HW, x = p - yy * HW;
        const float* row = sTmp + yy * TROW + x;
        float s0 = 0.f, s1 = 0.f, s2 = 0.f, s3 = 0.f;
#pragma unroll
        for (int t = 0; t < 68; t += 4) {
            s0 = fmaf(sW[t],     row[t],     s0);
            s1 = fmaf(sW[t + 1], row[t + 1], s1);
            s2 = fmaf(sW[t + 2], row[t + 2], s2);
            s3 = fmaf(sW[t + 3], row[t + 3], s3);
        }
        s0 = fmaf(sW[68], row[68], s0);
        s1 = fmaf(sW[69], row[69], s1);
        s2 = fmaf(sW[70], row[70], s2);
        dst[p] = (s0 + s1) + (s2 + s3);
    }
}

// ---------------- u8-A HMMA split-K GEMM ----------------
__global__ void __launch_bounds__(256, 1) k_gemm_mma() {
    extern __shared__ char dynRaw[];
    const uint32_t dynb = (s2u(dynRaw) + 1023u) & ~1023u;
    const int tid = threadIdx.x, w = tid >> 5, lid = tid & 31;
    const int m0 = blockIdx.x * 128;
    const int zbase = blockIdx.y * KHALF;

    const unsigned char* Abase = g_Ku + (size_t)m0 * NPIX + zbase;
    const __half* Bbase = g_qh + zbase;

    auto load_chunk = [&](int ci) {
        const uint32_t stage = dynb + (uint32_t)(ci % NSTAGE) * STAGE_BYTES;
        const int koff = ci * CHUNK;
#pragma unroll
        for (int u = tid; u < 1536; u += 256) {
            uint32_t dst; const void* src;
            if (u < 1024) {                 // A: 128 rows x 128B (u8)
                int r = u >> 3, t = u & 7;
                src = Abase + (size_t)r * NPIX + koff + t * 16;
                dst = stage + (uint32_t)(r * A_STRIDE + t * 16);
            } else {                        // B: 2 panels x 32 ch x 128B
                int v = u - 1024;
                int pl = v >> 8, cc = (v >> 3) & 31, t = v & 7;
                src = Bbase + (size_t)cc * NPIX + koff + pl * 64 + t * 8;
                dst = stage + A_PANEL + (uint32_t)pl * B_PANEL
                    + SWZ((uint32_t)(cc * 128 + t * 16));
            }
            CP16(dst, src);
        }
        CP_COMMIT();
    };

    float acc[3][4];
#pragma unroll
    for (int g = 0; g < 3; ++g)
#pragma unroll
        for (int k = 0; k < 4; ++k) acc[g][k] = 0.f;

    for (int i = 0; i < NSTAGE - 1; ++i) load_chunk(i);

    const uint32_t aBase0 = (uint32_t)((w * 16 + (lid >> 2)) * A_STRIDE + (lid & 3) * 2);
    const uint32_t bRowOff01 = (uint32_t)(((lid & 7) + ((lid >> 4) << 3)) * 128) + (((lid >> 3) & 1) << 4);
    const uint32_t bRowOff2 = (uint32_t)((16 + (lid & 7)) * 128) + (((lid >> 3) & 1) << 4);

    for (int i = 0; i < NCHUNK; ++i) {
        if (i + NSTAGE - 1 < NCHUNK) CP_WAIT(NSTAGE - 2); else CP_WAIT(0);
        __syncthreads();
        if (i + NSTAGE - 1 < NCHUNK) load_chunk(i + NSTAGE - 1);

        const uint32_t stage = dynb + (uint32_t)(i % NSTAGE) * STAGE_BYTES;
#pragma unroll
        for (int pl = 0; pl < 2; ++pl) {
            const uint32_t aP = stage + (uint32_t)pl * 64 + aBase0;
            const uint32_t bufB = stage + A_PANEL + (uint32_t)pl * B_PANEL;
#pragma unroll
            for (int ks = 0; ks < 4; ++ks) {
                const uint32_t ad = aP + (uint32_t)ks * 16;
                uint32_t w0, w1, w2, w3;
                LDSU16(w0, ad);
                LDSU16(w1, ad + 8 * A_STRIDE);
                LDSU16(w2, ad + 8);
                LDSU16(w3, ad + 8 * A_STRIDE + 8);
                const uint32_t a0 = u8x2_to_h2(w0);
                const uint32_t a1 = u8x2_to_h2(w1);
                const uint32_t a2 = u8x2_to_h2(w2);
                const uint32_t a3 = u8x2_to_h2(w3);

                const uint32_t kb = (uint32_t)ks * 32;
                uint32_t b00, b01, b10, b11, b20, b21;
                LDSM4(b00, b01, b10, b11, bufB + SWZ(bRowOff01 + kb));
                LDSM2(b20, b21, bufB + SWZ(bRowOff2 + kb));
                MMA16816(acc[0], a0, a1, a2, a3, b00, b01);
                MMA16816(acc[1], a0, a1, a2, a3, b10, b11);
                MMA16816(acc[2], a0, a1, a2, a3, b20, b21);
            }
        }
    }

    const int row0 = m0 + w * 16 + (lid >> 2);
    const int c0 = (lid & 3) * 2;
    float* pp = g_part + (size_t)blockIdx.y * (NCH * NPIX);
#pragma unroll
    for (int g = 0; g < 3; ++g) {
#pragma unroll
        for (int k = 0; k < 4; ++k) {
            int c = g * 8 + c0 + (k & 1);
            int row = row0 + ((k >> 1) << 3);
            if (c < NCH) pp[c * NPIX + row] = acc[g][k];
        }
    }
}

// ---------------- softmax update ----------------
__global__ void k_update(float* __restrict__ out, int final_it) {
    int i = blockIdx.x * blockDim.x + threadIdx.x;
    if (i >= NPIX) return;
    float ri = g_rowinv[i];
    float* dst = final_it ? out : g_q;

    float L[NCH];
    float m = -1e30f;
#pragma unroll
    for (int c = 0; c < NCH; ++c) {
        float s = g_part[c * NPIX + i] + g_part[(NCH + c) * NPIX + i];
        float l = g_U[c * NPIX + i] + (s * ri) * BSCALE + 2.0f * g_qsf[c * NPIX + i];
        L[c] = l;
        m = fmaxf(m, l);
    }
    float se = 0.f;
#pragma unroll
    for (int c = 0; c < NCH; ++c) { L[c] = __expf(L[c] - m); se += L[c]; }
    float inv = 1.0f / se;
#pragma unroll
    for (int c = 0; c < NCH; ++c) {
        float q = L[c] * inv;
        dst[c * NPIX + i] = q;
        g_qh[c * NPIX + i] = __float2half_rn(q * ri);
    }
}

// ---------------- launch ----------------
extern "C" void kernel_launch(void* const* d_in, const int* in_sizes, int n_in,
                              void* d_out, int out_size) {
    const float* unary = nullptr;
    const float* ref = nullptr;
    const float* kstd = nullptr;
    for (int i = 0; i < n_in; ++i) {
        if (in_sizes[i] == NCH * NPIX) unary = (const float*)d_in[i];
        else if (in_sizes[i] == 3 * NPIX) ref = (const float*)d_in[i];
        else if (in_sizes[i] == 5) kstd = (const float*)d_in[i];
    }

    cudaFuncSetAttribute(k_gemm_mma, cudaFuncAttributeMaxDynamicSharedMemorySize, GEMM_SMEM);

    k_feat<<<(NPIX + 255) / 256, 256>>>(ref, kstd);
    k_K<<<dim3(NPIX / 128, NPIX / 32), 256>>>();
    k_init<<<(NPIX + 255) / 256, 256>>>(unary);

    for (int it = 0; it < 5; ++it) {
        k_conv<<<NCH * STRIPS, 384>>>();
        k_gemm_mma<<<dim3(MTILES, KSPLIT), 256, GEMM_SMEM>>>();
        k_update<<<(NPIX + 255) / 256, 256>>>((float*)d_out, it == 4 ? 1 : 0);
    }
}

// round 10
// speedup vs baseline: 1.1806x; 1.0623x over previous
#include <cuda_runtime.h>
#include <cuda_fp16.h>
#include <math.h>
#include <cstdint>

#define HW      96
#define NPIX    9216
#define NCH     21
#define RAD     35
#define KW      71
#define KSPLIT  4
#define KSLICE  2304          // NPIX / KSPLIT
#define CHUNK   128           // k per pipeline chunk
#define NCHUNK  18            // KSLICE / CHUNK
#define NSTAGE  4
#define A_STRIDE 144
#define A_PANEL (256 * A_STRIDE)   // 36864
#define B_PANEL 4096               // 32 ch * 128B (64 k fp16, swizzled)
#define STAGE_BYTES (A_PANEL + 2 * B_PANEL)  // 45056
#define MTILES  72            // col-tiles in k_K
#define GTILES  36            // NPIX / 256
#define GEMM_SMEM (NSTAGE * STAGE_BYTES + 1024)
#define STRIPS  6
#define SROWS   16
#define HALO    86
#define TROW    (HW + 2 * RAD)
#define BSCALE  (4.0f / 255.0f)

// ---------------- device scratch ----------------
__device__ unsigned char g_Ku[(size_t)NPIX * NPIX];  // 85 MB u8 kernel matrix
__device__ float  g_feat[5][NPIX];
__device__ float  g_nhalf[NPIX];                     // -0.5*|f|^2
__device__ float  g_rowpart[NPIX * MTILES];
__device__ float  g_rowinv[NPIX];
__device__ float  g_U[NCH * NPIX];
__device__ float  g_q[NCH * NPIX];
__device__ __half g_qh[32 * NPIX];
__device__ float  g_part[KSPLIT * NCH * NPIX];
__device__ float  g_qsf[NCH * NPIX];
__device__ float  g_g1d[KW];

// ---------------- PTX helpers ----------------
__device__ __forceinline__ uint32_t s2u(const void* p) {
    uint32_t a;
    asm("{ .reg .u64 t; cvta.to.shared.u64 t, %1; cvt.u32.u64 %0, t; }" : "=r"(a) : "l"(p));
    return a;
}
#define SWZ(b) ((b) ^ (((b) >> 3) & 0x70))
#define CP16(dst, src) \
    asm volatile("cp.async.cg.shared.global [%0], [%1], 16;" :: "r"(dst), "l"(src) : "memory")
#define CP_COMMIT() asm volatile("cp.async.commit_group;" ::: "memory")
#define CP_WAIT(n)  asm volatile("cp.async.wait_group %0;" :: "n"(n) : "memory")
#define LDSU16(r, addr) \
    asm volatile("ld.shared.u16 %0, [%1];" : "=r"(r) : "r"(addr))
#define LDSM4(r0, r1, r2, r3, addr) \
    asm volatile("ldmatrix.sync.aligned.m8n8.x4.shared.b16 {%0,%1,%2,%3}, [%4];" \
                 : "=r"(r0), "=r"(r1), "=r"(r2), "=r"(r3) : "r"(addr))
#define LDSM2(r0, r1, addr) \
    asm volatile("ldmatrix.sync.aligned.m8n8.x2.shared.b16 {%0,%1}, [%2];" \
                 : "=r"(r0), "=r"(r1) : "r"(addr))
#define MMA16816(d, a0, a1, a2, a3, b0, b1) \
    asm volatile("mma.sync.aligned.m16n8k16.row.col.f32.f16.f16.f32 " \
                 "{%0,%1,%2,%3}, {%4,%5,%6,%7}, {%8,%9}, {%0,%1,%2,%3};" \
                 : "+f"((d)[0]), "+f"((d)[1]), "+f"((d)[2]), "+f"((d)[3]) \
                 : "r"(a0), "r"(a1), "r"(a2), "r"(a3), "r"(b0), "r"(b1))

// two u8 -> packed fp16x2 exact ints
__device__ __forceinline__ uint32_t u8x2_to_h2(uint32_t w) {
    uint32_t r;
    asm("prmt.b32 %0, %1, 0, 0x4140;" : "=r"(r) : "r"(w));
    r |= 0x64006400u;
    asm("sub.rn.f16x2 %0, %0, %1;" : "+r"(r) : "r"(0x64006400u));
    return r;
}

// ---------------- setup ----------------
__global__ void k_feat(const float* __restrict__ ref, const float* __restrict__ kstd) {
    if (blockIdx.x == 0 && threadIdx.x == 0) {
        float w[KW]; float s = 0.f;
        for (int t = 0; t < KW; ++t) {
            float d = (float)t - (float)RAD;
            w[t] = expf(-(d * d) / 72.0f); s += w[t];
        }
        float inv = 1.0f / s;
        for (int t = 0; t < KW; ++t) g_g1d[t] = w[t] * inv;
    }
    int i = blockIdx.x * blockDim.x + threadIdx.x;
    if (i >= NPIX) return;
    int y = i / HW, x = i % HW;
    float f0 = (float)y / kstd[0];
    float f1 = (float)x / kstd[1];
    float f2 = ref[0 * NPIX + i] / kstd[2];
    float f3 = ref[1 * NPIX + i] / kstd[3];
    float f4 = ref[2 * NPIX + i] / kstd[4];
    g_feat[0][i] = f0; g_feat[1][i] = f1; g_feat[2][i] = f2;
    g_feat[3][i] = f3; g_feat[4][i] = f4;
    g_nhalf[i] = -0.5f * (f0 * f0 + f1 * f1 + f2 * f2 + f3 * f3 + f4 * f4);
}

// K tile via dot form: exp(nr + nc + dot)
__global__ void __launch_bounds__(256) k_K() {
    __shared__ float s_fr[5][32];
    __shared__ float s_fc[5][128];
    __shared__ float s_nr[32];
    __shared__ float s_nc[128];
    const int rowBase = blockIdx.y * 32;
    const int colBase = blockIdx.x * 128;
    const int tid = threadIdx.x;

    if (tid < 5 * 32) { int d = tid / 32, rr = tid % 32; s_fr[d][rr] = g_feat[d][rowBase + rr]; }
    if (tid < 32) s_nr[tid] = g_nhalf[rowBase + tid];
    for (int idx = tid; idx < 5 * 128; idx += 256) {
        int d = idx / 128, cc = idx % 128;
        s_fc[d][cc] = g_feat[d][colBase + cc];
    }
    if (tid < 128) s_nc[tid] = g_nhalf[colBase + tid];
    __syncthreads();

    const int r = tid >> 5;
    const int cl = tid & 31;

    float fr[4][5], fc[4][5], nr[4], nc[4];
#pragma unroll
    for (int a = 0; a < 4; ++a) {
#pragma unroll
        for (int d = 0; d < 5; ++d) fr[a][d] = s_fr[d][r * 4 + a];
        nr[a] = s_nr[r * 4 + a];
    }
#pragma unroll
    for (int b = 0; b < 4; ++b) {
#pragma unroll
        for (int d = 0; d < 5; ++d) fc[b][d] = s_fc[d][cl + 32 * b];
        nc[b] = s_nc[cl + 32 * b];
    }

#pragma unroll
    for (int a = 0; a < 4; ++a) {
        const int row = rowBase + r * 4 + a;
        const size_t rowOff = (size_t)row * NPIX;
        float rs = 0.f;
#pragma unroll
        for (int b = 0; b < 4; ++b) {
            float dot = nr[a] + nc[b];
#pragma unroll
            for (int d = 0; d < 5; ++d) dot = fmaf(fr[a][d], fc[b][d], dot);
            float v = __expf(dot);
            rs += v;
            g_Ku[rowOff + colBase + cl + 32 * b] =
                (unsigned char)__float2uint_rn(v * 255.0f);
        }
#pragma unroll
        for (int o = 16; o; o >>= 1) rs += __shfl_xor_sync(0xffffffffu, rs, o);
        if (cl == 0) g_rowpart[row * MTILES + blockIdx.x] = rs;
    }
}

__global__ void k_init(const float* __restrict__ unary) {
    int i = blockIdx.x * blockDim.x + threadIdx.x;
    if (i >= NPIX) return;
    float s = 0.f;
    const float* p = g_rowpart + i * MTILES;
#pragma unroll
    for (int b = 0; b < MTILES; ++b) s += p[b];
    float ri = 1.0f / (sqrtf(s) + 1e-8f);
    g_rowinv[i] = ri;

    float L[NCH];
    float m = -1e30f;
#pragma unroll
    for (int c = 0; c < NCH; ++c) {
        float u = unary[c * NPIX + i];
        u = fminf(fmaxf(u, 1e-5f), 1.0f);
        float lu = logf(u);
        g_U[c * NPIX + i] = lu;
        L[c] = lu;
        m = fmaxf(m, lu);
    }
    float se = 0.f;
#pragma unroll
    for (int c = 0; c < NCH; ++c) { L[c] = __expf(L[c] - m); se += L[c]; }
    float inv = 1.0f / se;
#pragma unroll
    for (int c = 0; c < NCH; ++c) {
        float q = L[c] * inv;
        g_q[c * NPIX + i] = q;
        g_qh[c * NPIX + i] = __float2half_rn(q * ri);
    }
#pragma unroll
    for (int c = NCH; c < 32; ++c) g_qh[c * NPIX + i] = __float2half_rn(0.f);
}

// ---------------- strip-parallel separable conv ----------------
__global__ void __launch_bounds__(384) k_conv() {
    __shared__ float sImg[HALO * HW];
    __shared__ float sTmp[SROWS * TROW];
    __shared__ float sW[KW];
    const int c = blockIdx.x / STRIPS;
    const int strip = blockIdx.x % STRIPS;
    const int y0 = strip * SROWS;
    const int rowLo = y0 - RAD;
    const int tid = threadIdx.x;

    if (tid < KW) sW[tid] = g_g1d[tid];
    const float* src = g_q + c * NPIX;
    for (int p = tid; p < HALO * HW; p += 384) {
        int r = p / HW, x = p - r * HW;
        int gr = rowLo + r;
        sImg[p] = (gr >= 0 && gr < HW) ? src[gr * HW + x] : 0.f;
    }
    for (int p = tid; p < SROWS * TROW; p += 384) sTmp[p] = 0.f;
    __syncthreads();

    for (int p = tid; p < SROWS * HW; p += 384) {
        int yy = p / HW, x = p - yy * HW;
        const float* col = sImg + yy * HW + x;
        float s0 = 0.f, s1 = 0.f, s2 = 0.f, s3 = 0.f;
#pragma unroll
        for (int t = 0; t < 68; t += 4) {
            s0 = fmaf(sW[t],     col[t * HW],       s0);
            s1 = fmaf(sW[t + 1], col[(t + 1) * HW], s1);
            s2 = fmaf(sW[t + 2], col[(t + 2) * HW], s2);
            s3 = fmaf(sW[t + 3], col[(t + 3) * HW], s3);
        }
        s0 = fmaf(sW[68], col[68 * HW], s0);
        s1 = fmaf(sW[69], col[69 * HW], s1);
        s2 = fmaf(sW[70], col[70 * HW], s2);
        sTmp[yy * TROW + RAD + x] = (s0 + s1) + (s2 + s3);
    }
    __syncthreads();

    float* dst = g_qsf + c * NPIX + y0 * HW;
    for (int p = tid; p < SROWS * HW; p += 384) {
        int yy = p / HW, x = p - yy * HW;
        const float* row = sTmp + yy * TROW + x;
        float s0 = 0.f, s1 = 0.f, s2 = 0.f, s3 = 0.f;
#pragma unroll
        for (int t = 0; t < 68; t += 4) {
            s0 = fmaf(sW[t],     row[t],     s0);
            s1 = fmaf(sW[t + 1], row[t + 1], s1);
            s2 = fmaf(sW[t + 2], row[t + 2], s2);
            s3 = fmaf(sW[t + 3], row[t + 3], s3);
        }
        s0 = fmaf(sW[68], row[68], s0);
        s1 = fmaf(sW[69], row[69], s1);
        s2 = fmaf(sW[70], row[70], s2);
        dst[p] = (s0 + s1) + (s2 + s3);
    }
}

// ---------------- u8-A HMMA GEMM: M-tile 256, 32 rows/warp, KSPLIT=4 ----------------
__global__ void __launch_bounds__(256, 1) k_gemm_mma() {
    extern __shared__ char dynRaw[];
    const uint32_t dynb = (s2u(dynRaw) + 1023u) & ~1023u;
    const int tid = threadIdx.x, w = tid >> 5, lid = tid & 31;
    const int m0 = blockIdx.x * 256;
    const int zbase = blockIdx.y * KSLICE;

    const unsigned char* Abase = g_Ku + (size_t)m0 * NPIX + zbase;
    const __half* Bbase = g_qh + zbase;

    auto load_chunk = [&](int ci) {
        const uint32_t stage = dynb + (uint32_t)(ci % NSTAGE) * STAGE_BYTES;
        const int koff = ci * CHUNK;
#pragma unroll
        for (int u = tid; u < 2560; u += 256) {
            uint32_t dst; const void* src;
            if (u < 2048) {                 // A: 256 rows x 128B (u8)
                int r = u >> 3, t = u & 7;
                src = Abase + (size_t)r * NPIX + koff + t * 16;
                dst = stage + (uint32_t)(r * A_STRIDE + t * 16);
            } else {                        // B: 2 panels x 32 ch x 128B
                int v = u - 2048;
                int pl = v >> 8, cc = (v >> 3) & 31, t = v & 7;
                src = Bbase + (size_t)cc * NPIX + koff + pl * 64 + t * 8;
                dst = stage + A_PANEL + (uint32_t)pl * B_PANEL
                    + SWZ((uint32_t)(cc * 128 + t * 16));
            }
            CP16(dst, src);
        }
        CP_COMMIT();
    };

    float acc[2][3][4];
#pragma unroll
    for (int f = 0; f < 2; ++f)
#pragma unroll
        for (int g = 0; g < 3; ++g)
#pragma unroll
            for (int k = 0; k < 4; ++k) acc[f][g][k] = 0.f;

    for (int i = 0; i < NSTAGE - 1; ++i) load_chunk(i);

    // warp w owns rows [w*32, w*32+32): two m16 fragments at +0 and +16
    const uint32_t aBase0 = (uint32_t)((w * 32 + (lid >> 2)) * A_STRIDE + (lid & 3) * 2);
    const uint32_t aBase1 = aBase0 + 16 * A_STRIDE;
    const uint32_t bRowOff01 = (uint32_t)(((lid & 7) + ((lid >> 4) << 3)) * 128) + (((lid >> 3) & 1) << 4);
    const uint32_t bRowOff2 = (uint32_t)((16 + (lid & 7)) * 128) + (((lid >> 3) & 1) << 4);

    for (int i = 0; i < NCHUNK; ++i) {
        if (i + NSTAGE - 1 < NCHUNK) CP_WAIT(NSTAGE - 2); else CP_WAIT(0);
        __syncthreads();
        if (i + NSTAGE - 1 < NCHUNK) load_chunk(i + NSTAGE - 1);

        const uint32_t stage = dynb + (uint32_t)(i % NSTAGE) * STAGE_BYTES;
#pragma unroll
        for (int pl = 0; pl < 2; ++pl) {
            const uint32_t aOff = stage + (uint32_t)pl * 64;
            const uint32_t bufB = stage + A_PANEL + (uint32_t)pl * B_PANEL;
#pragma unroll
            for (int ks = 0; ks < 4; ++ks) {
                const uint32_t kb = (uint32_t)ks * 32;
                uint32_t b00, b01, b10, b11, b20, b21;
                LDSM4(b00, b01, b10, b11, bufB + SWZ(bRowOff01 + kb));
                LDSM2(b20, b21, bufB + SWZ(bRowOff2 + kb));

                const uint32_t ad0 = aOff + aBase0 + (uint32_t)ks * 16;
                const uint32_t ad1 = aOff + aBase1 + (uint32_t)ks * 16;
                uint32_t w0, w1, w2, w3, w4, w5, w6, w7;
                LDSU16(w0, ad0);
                LDSU16(w1, ad0 + 8 * A_STRIDE);
                LDSU16(w2, ad0 + 8);
                LDSU16(w3, ad0 + 8 * A_STRIDE + 8);
                LDSU16(w4, ad1);
                LDSU16(w5, ad1 + 8 * A_STRIDE);
                LDSU16(w6, ad1 + 8);
                LDSU16(w7, ad1 + 8 * A_STRIDE + 8);
                const uint32_t a00 = u8x2_to_h2(w0);
                const uint32_t a01 = u8x2_to_h2(w1);
                const uint32_t a02 = u8x2_to_h2(w2);
                const uint32_t a03 = u8x2_to_h2(w3);
                const uint32_t a10 = u8x2_to_h2(w4);
                const uint32_t a11 = u8x2_to_h2(w5);
                const uint32_t a12 = u8x2_to_h2(w6);
                const uint32_t a13 = u8x2_to_h2(w7);

                MMA16816(acc[0][0], a00, a01, a02, a03, b00, b01);
                MMA16816(acc[0][1], a00, a01, a02, a03, b10, b11);
                MMA16816(acc[0][2], a00, a01, a02, a03, b20, b21);
                MMA16816(acc[1][0], a10, a11, a12, a13, b00, b01);
                MMA16816(acc[1][1], a10, a11, a12, a13, b10, b11);
                MMA16816(acc[1][2], a10, a11, a12, a13, b20, b21);
            }
        }
    }

    const int c0 = (lid & 3) * 2;
    float* pp = g_part + (size_t)blockIdx.y * (NCH * NPIX);
#pragma unroll
    for (int f = 0; f < 2; ++f) {
        const int row0 = m0 + w * 32 + f * 16 + (lid >> 2);
#pragma unroll
        for (int g = 0; g < 3; ++g) {
#pragma unroll
            for (int k = 0; k < 4; ++k) {
                int c = g * 8 + c0 + (k & 1);
                int row = row0 + ((k >> 1) << 3);
                if (c < NCH) pp[c * NPIX + row] = acc[f][g][k];
            }
        }
    }
}

// ---------------- softmax update ----------------
__global__ void k_update(float* __restrict__ out, int final_it) {
    int i = blockIdx.x * blockDim.x + threadIdx.x;
    if (i >= NPIX) return;
    float ri = g_rowinv[i];
    float* dst = final_it ? out : g_q;

    float L[NCH];
    float m = -1e30f;
#pragma unroll
    for (int c = 0; c < NCH; ++c) {
        float s = g_part[c * NPIX + i] + g_part[(NCH + c) * NPIX + i]
                + g_part[(2 * NCH + c) * NPIX + i] + g_part[(3 * NCH + c) * NPIX + i];
        float l = g_U[c * NPIX + i] + (s * ri) * BSCALE + 2.0f * g_qsf[c * NPIX + i];
        L[c] = l;
        m = fmaxf(m, l);
    }
    float se = 0.f;
#pragma unroll
    for (int c = 0; c < NCH; ++c) { L[c] = __expf(L[c] - m); se += L[c]; }
    float inv = 1.0f / se;
#pragma unroll
    for (int c = 0; c < NCH; ++c) {
        float q = L[c] * inv;
        dst[c * NPIX + i] = q;
        g_qh[c * NPIX + i] = __float2half_rn(q * ri);
    }
}

// ---------------- launch ----------------
extern "C" void kernel_launch(void* const* d_in, const int* in_sizes, int n_in,
                              void* d_out, int out_size) {
    const float* unary = nullptr;
    const float* ref = nullptr;
    const float* kstd = nullptr;
    for (int i = 0; i < n_in; ++i) {
        if (in_sizes[i] == NCH * NPIX) unary = (const float*)d_in[i];
        else if (in_sizes[i] == 3 * NPIX) ref = (const float*)d_in[i];
        else if (in_sizes[i] == 5) kstd = (const float*)d_in[i];
    }

    cudaFuncSetAttribute(k_gemm_mma, cudaFuncAttributeMaxDynamicSharedMemorySize, GEMM_SMEM);

    k_feat<<<(NPIX + 255) / 256, 256>>>(ref, kstd);
    k_K<<<dim3(NPIX / 128, NPIX / 32), 256>>>();
    k_init<<<(NPIX + 255) / 256, 256>>>(unary);

    for (int it = 0; it < 5; ++it) {
        k_conv<<<NCH * STRIPS, 384>>>();
        k_gemm_mma<<<dim3(GTILES, KSPLIT), 256, GEMM_SMEM>>>();
        k_update<<<(NPIX + 255) / 256, 256>>>((float*)d_out, it == 4 ? 1 : 0);
    }
}

// round 11
// speedup vs baseline: 1.1815x; 1.0008x over previous
#include <cuda_runtime.h>
#include <cuda_fp16.h>
#include <math.h>
#include <cstdint>

#define HW      96
#define NPIX    9216
#define NCH     21
#define RAD     35
#define KW      71
#define KSPLIT  4
#define KSLICE  2304          // NPIX / KSPLIT
#define CHUNK   128           // k per pipeline chunk (2 panels of 64)
#define NCHUNK  18            // KSLICE / CHUNK
#define NSTAGE  5
#define A_PANEL 16384         // 256 rows * 64B permuted
#define B_PANEL 4096          // 32 ch * 128B (64 k fp16, swizzled)
#define STAGE_BYTES (2 * A_PANEL + 2 * B_PANEL)  // 40960
#define MTILES  72
#define GTILES  36            // NPIX / 256
#define GEMM_SMEM (NSTAGE * STAGE_BYTES + 1024)
#define STRIPS  6
#define SROWS   16
#define HALO    86
#define TROW    (HW + 2 * RAD)
#define BSCALE  (4.0f / 255.0f)

// ---------------- device scratch ----------------
__device__ unsigned char g_Ku[(size_t)NPIX * NPIX];  // 85 MB u8, fragment-permuted rows
__device__ float  g_feat[5][NPIX];
__device__ float  g_nhalf[NPIX];
__device__ float  g_rowpart[NPIX * MTILES];
__device__ float  g_rowinv[NPIX];
__device__ float  g_U[NCH * NPIX];
__device__ float  g_q[NCH * NPIX];
__device__ __half g_qh[32 * NPIX];
__device__ float  g_part[KSPLIT * NCH * NPIX];
__device__ float  g_qsf[NCH * NPIX];
__device__ float  g_g1d[KW];

// ---------------- PTX helpers ----------------
__device__ __forceinline__ uint32_t s2u(const void* p) {
    uint32_t a;
    asm("{ .reg .u64 t; cvta.to.shared.u64 t, %1; cvt.u32.u64 %0, t; }" : "=r"(a) : "l"(p));
    return a;
}
#define SWZ(b) ((b) ^ (((b) >> 3) & 0x70))
#define CP16(dst, src) \
    asm volatile("cp.async.cg.shared.global [%0], [%1], 16;" :: "r"(dst), "l"(src) : "memory")
#define CP_COMMIT() asm volatile("cp.async.commit_group;" ::: "memory")
#define CP_WAIT(n)  asm volatile("cp.async.wait_group %0;" :: "n"(n) : "memory")
#define LDS128(r0, r1, r2, r3, addr) \
    asm volatile("ld.shared.v4.u32 {%0,%1,%2,%3}, [%4];" \
                 : "=r"(r0), "=r"(r1), "=r"(r2), "=r"(r3) : "r"(addr))
#define LDSM4(r0, r1, r2, r3, addr) \
    asm volatile("ldmatrix.sync.aligned.m8n8.x4.shared.b16 {%0,%1,%2,%3}, [%4];" \
                 : "=r"(r0), "=r"(r1), "=r"(r2), "=r"(r3) : "r"(addr))
#define LDSM2(r0, r1, addr) \
    asm volatile("ldmatrix.sync.aligned.m8n8.x2.shared.b16 {%0,%1}, [%2];" \
                 : "=r"(r0), "=r"(r1) : "r"(addr))
#define MMA16816(d, a0, a1, a2, a3, b0, b1) \
    asm volatile("mma.sync.aligned.m16n8k16.row.col.f32.f16.f16.f32 " \
                 "{%0,%1,%2,%3}, {%4,%5,%6,%7}, {%8,%9}, {%0,%1,%2,%3};" \
                 : "+f"((d)[0]), "+f"((d)[1]), "+f"((d)[2]), "+f"((d)[3]) \
                 : "r"(a0), "r"(a1), "r"(a2), "r"(a3), "r"(b0), "r"(b1))

// bytes (sel-chosen pair) of w -> packed fp16x2 exact ints 0..255
__device__ __forceinline__ uint32_t h2lo(uint32_t w) {
    uint32_t r;
    asm("prmt.b32 %0, %1, 0, 0x4140;" : "=r"(r) : "r"(w));
    r |= 0x64006400u;
    asm("sub.rn.f16x2 %0, %0, %1;" : "+r"(r) : "r"(0x64006400u));
    return r;
}
__device__ __forceinline__ uint32_t h2hi(uint32_t w) {
    uint32_t r;
    asm("prmt.b32 %0, %1, 0, 0x4342;" : "=r"(r) : "r"(w));
    r |= 0x64006400u;
    asm("sub.rn.f16x2 %0, %0, %1;" : "+r"(r) : "r"(0x64006400u));
    return r;
}

// ---------------- setup ----------------
__global__ void k_feat(const float* __restrict__ ref, const float* __restrict__ kstd) {
    if (blockIdx.x == 0 && threadIdx.x == 0) {
        float w[KW]; float s = 0.f;
        for (int t = 0; t < KW; ++t) {
            float d = (float)t - (float)RAD;
            w[t] = expf(-(d * d) / 72.0f); s += w[t];
        }
        float inv = 1.0f / s;
        for (int t = 0; t < KW; ++t) g_g1d[t] = w[t] * inv;
    }
    int i = blockIdx.x * blockDim.x + threadIdx.x;
    if (i >= NPIX) return;
    int y = i / HW, x = i % HW;
    float f0 = (float)y / kstd[0];
    float f1 = (float)x / kstd[1];
    float f2 = ref[0 * NPIX + i] / kstd[2];
    float f3 = ref[1 * NPIX + i] / kstd[3];
    float f4 = ref[2 * NPIX + i] / kstd[4];
    g_feat[0][i] = f0; g_feat[1][i] = f1; g_feat[2][i] = f2;
    g_feat[3][i] = f3; g_feat[4][i] = f4;
    g_nhalf[i] = -0.5f * (f0 * f0 + f1 * f1 + f2 * f2 + f3 * f3 + f4 * f4);
}

// K tile (dot form), stored with fragment permutation inside each 64-col block
__global__ void __launch_bounds__(256) k_K() {
    __shared__ float s_fr[5][32];
    __shared__ float s_fc[5][128];
    __shared__ float s_nr[32];
    __shared__ float s_nc[128];
    const int rowBase = blockIdx.y * 32;
    const int colBase = blockIdx.x * 128;
    const int tid = threadIdx.x;

    if (tid < 5 * 32) { int d = tid / 32, rr = tid % 32; s_fr[d][rr] = g_feat[d][rowBase + rr]; }
    if (tid < 32) s_nr[tid] = g_nhalf[rowBase + tid];
    for (int idx = tid; idx < 5 * 128; idx += 256) {
        int d = idx / 128, cc = idx % 128;
        s_fc[d][cc] = g_feat[d][colBase + cc];
    }
    if (tid < 128) s_nc[tid] = g_nhalf[colBase + tid];
    __syncthreads();

    const int r = tid >> 5;
    const int cl = tid & 31;

    float fr[4][5], fc[4][5], nr[4], nc[4];
#pragma unroll
    for (int a = 0; a < 4; ++a) {
#pragma unroll
        for (int d = 0; d < 5; ++d) fr[a][d] = s_fr[d][r * 4 + a];
        nr[a] = s_nr[r * 4 + a];
    }
#pragma unroll
    for (int b = 0; b < 4; ++b) {
#pragma unroll
        for (int d = 0; d < 5; ++d) fc[b][d] = s_fc[d][cl + 32 * b];
        nc[b] = s_nc[cl + 32 * b];
    }

#pragma unroll
    for (int a = 0; a < 4; ++a) {
        const int row = rowBase + r * 4 + a;
        const size_t rowOff = (size_t)row * NPIX;
        float rs = 0.f;
#pragma unroll
        for (int b = 0; b < 4; ++b) {
            float dot = nr[a] + nc[b];
#pragma unroll
            for (int d = 0; d < 5; ++d) dot = fmaf(fr[a][d], fc[b][d], dot);
            float v = __expf(dot);
            rs += v;
            int col = colBase + cl + 32 * b;
            int j = col & 63;
            int s = ((j & 6) << 3) | (((j >> 4) & 3) << 2) | (((j >> 3) & 1) << 1) | (j & 1);
            g_Ku[rowOff + (size_t)(col & ~63) + s] =
                (unsigned char)__float2uint_rn(v * 255.0f);
        }
#pragma unroll
        for (int o = 16; o; o >>= 1) rs += __shfl_xor_sync(0xffffffffu, rs, o);
        if (cl == 0) g_rowpart[row * MTILES + blockIdx.x] = rs;
    }
}

__global__ void k_init(const float* __restrict__ unary) {
    int i = blockIdx.x * blockDim.x + threadIdx.x;
    if (i >= NPIX) return;
    float s = 0.f;
    const float* p = g_rowpart + i * MTILES;
#pragma unroll
    for (int b = 0; b < MTILES; ++b) s += p[b];
    float ri = 1.0f / (sqrtf(s) + 1e-8f);
    g_rowinv[i] = ri;

    float L[NCH];
    float m = -1e30f;
#pragma unroll
    for (int c = 0; c < NCH; ++c) {
        float u = unary[c * NPIX + i];
        u = fminf(fmaxf(u, 1e-5f), 1.0f);
        float lu = logf(u);
        g_U[c * NPIX + i] = lu;
        L[c] = lu;
        m = fmaxf(m, lu);
    }
    float se = 0.f;
#pragma unroll
    for (int c = 0; c < NCH; ++c) { L[c] = __expf(L[c] - m); se += L[c]; }
    float inv = 1.0f / se;
#pragma unroll
    for (int c = 0; c < NCH; ++c) {
        float q = L[c] * inv;
        g_q[c * NPIX + i] = q;
        g_qh[c * NPIX + i] = __float2half_rn(q * ri);
    }
#pragma unroll
    for (int c = NCH; c < 32; ++c) g_qh[c * NPIX + i] = __float2half_rn(0.f);
}

// ---------------- strip-parallel separable conv ----------------
__global__ void __launch_bounds__(384) k_conv() {
    __shared__ float sImg[HALO * HW];
    __shared__ float sTmp[SROWS * TROW];
    __shared__ float sW[KW];
    const int c = blockIdx.x / STRIPS;
    const int strip = blockIdx.x % STRIPS;
    const int y0 = strip * SROWS;
    const int rowLo = y0 - RAD;
    const int tid = threadIdx.x;

    if (tid < KW) sW[tid] = g_g1d[tid];
    const float* src = g_q + c * NPIX;
    for (int p = tid; p < HALO * HW; p += 384) {
        int r = p / HW, x = p - r * HW;
        int gr = rowLo + r;
        sImg[p] = (gr >= 0 && gr < HW) ? src[gr * HW + x] : 0.f;
    }
    for (int p = tid; p < SROWS * TROW; p += 384) sTmp[p] = 0.f;
    __syncthreads();

    for (int p = tid; p < SROWS * HW; p += 384) {
        int yy = p / HW, x = p - yy * HW;
        const float* col = sImg + yy * HW + x;
        float s0 = 0.f, s1 = 0.f, s2 = 0.f, s3 = 0.f;
#pragma unroll
        for (int t = 0; t < 68; t += 4) {
            s0 = fmaf(sW[t],     col[t * HW],       s0);
            s1 = fmaf(sW[t + 1], col[(t + 1) * HW], s1);
            s2 = fmaf(sW[t + 2], col[(t + 2) * HW], s2);
            s3 = fmaf(sW[t + 3], col[(t + 3) * HW], s3);
        }
        s0 = fmaf(sW[68], col[68 * HW], s0);
        s1 = fmaf(sW[69], col[69 * HW], s1);
        s2 = fmaf(sW[70], col[70 * HW], s2);
        sTmp[yy * TROW + RAD + x] = (s0 + s1) + (s2 + s3);
    }
    __syncthreads();

    float* dst = g_qsf + c * NPIX + y0 * HW;
    for (int p = tid; p < SROWS * HW; p += 384) {
        int yy = p / HW, x = p - yy * HW;
        const float* row = sTmp + yy * TROW + x;
        float s0 = 0.f, s1 = 0.f, s2 = 0.f, s3 = 0.f;
#pragma unroll
        for (int t = 0; t < 68; t += 4) {
            s0 = fmaf(sW[t],     row[t],     s0);
            s1 = fmaf(sW[t + 1], row[t + 1], s1);
            s2 = fmaf(sW[t + 2], row[t + 2], s2);
            s3 = fmaf(sW[t + 3], row[t + 3], s3);
        }
        s0 = fmaf(sW[68], row[68], s0);
        s1 = fmaf(sW[69], row[69], s1);
        s2 = fmaf(sW[70], row[70], s2);
        dst[p] = (s0 + s1) + (s2 + s3);
    }
}

// ---------------- u8-A HMMA GEMM: permuted A, one LDS.128 per panel/mfrag/row-half ----------------
__global__ void __launch_bounds__(256, 1) k_gemm_mma() {
    extern __shared__ char dynRaw[];
    const uint32_t dynb = (s2u(dynRaw) + 1023u) & ~1023u;
    const int tid = threadIdx.x, w = tid >> 5, lid = tid & 31;
    const int m0 = blockIdx.x * 256;
    const int zbase = blockIdx.y * KSLICE;

    const unsigned char* Abase = g_Ku + (size_t)m0 * NPIX + zbase;
    const __half* Bbase = g_qh + zbase;

    auto load_chunk = [&](int ci) {
        const uint32_t stage = dynb + (uint32_t)(ci % NSTAGE) * STAGE_BYTES;
        const int koff = ci * CHUNK;
#pragma unroll
        for (int u = tid; u < 2560; u += 256) {
            uint32_t dst; const void* src;
            if (u < 2048) {                 // A: 256 rows x 128B (2 permuted 64B blocks)
                int r = u >> 3, t = u & 7;
                src = Abase + (size_t)r * NPIX + koff + t * 16;
                dst = stage + (uint32_t)((t >> 2) * A_PANEL + r * 64 + (t & 3) * 16);
            } else {                        // B: 2 panels x 32 ch x 128B
                int v = u - 2048;
                int pl = v >> 8, cc = (v >> 3) & 31, t = v & 7;
                src = Bbase + (size_t)cc * NPIX + koff + pl * 64 + t * 8;
                dst = stage + 2 * A_PANEL + (uint32_t)pl * B_PANEL
                    + SWZ((uint32_t)(cc * 128 + t * 16));
            }
            CP16(dst, src);
        }
        CP_COMMIT();
    };

    float acc[2][3][4];
#pragma unroll
    for (int f = 0; f < 2; ++f)
#pragma unroll
        for (int g = 0; g < 3; ++g)
#pragma unroll
            for (int k = 0; k < 4; ++k) acc[f][g][k] = 0.f;

    for (int i = 0; i < NSTAGE - 1; ++i) load_chunk(i);

    // warp w owns rows [w*32, w*32+32); per-thread A base within a panel
    const uint32_t aBase = (uint32_t)((w * 32 + (lid >> 2)) * 64 + (lid & 3) * 16);
    const uint32_t bRowOff01 = (uint32_t)(((lid & 7) + ((lid >> 4) << 3)) * 128) + (((lid >> 3) & 1) << 4);
    const uint32_t bRowOff2 = (uint32_t)((16 + (lid & 7)) * 128) + (((lid >> 3) & 1) << 4);

    for (int i = 0; i < NCHUNK; ++i) {
        if (i + NSTAGE - 1 < NCHUNK) CP_WAIT(NSTAGE - 2); else CP_WAIT(0);
        __syncthreads();
        if (i + NSTAGE - 1 < NCHUNK) load_chunk(i + NSTAGE - 1);

        const uint32_t stage = dynb + (uint32_t)(i % NSTAGE) * STAGE_BYTES;
#pragma unroll
        for (int pl = 0; pl < 2; ++pl) {
            const uint32_t aP = stage + (uint32_t)pl * A_PANEL + aBase;
            const uint32_t bufB = stage + 2 * A_PANEL + (uint32_t)pl * B_PANEL;
            // A00: mfrag0 rows lid>>2 (a0,a2 for ks0..3); A01: +8 rows (a1,a3)
            uint32_t A00[4], A01[4], A10[4], A11[4];
            LDS128(A00[0], A00[1], A00[2], A00[3], aP);
            LDS128(A01[0], A01[1], A01[2], A01[3], aP + 8 * 64);
            LDS128(A10[0], A10[1], A10[2], A10[3], aP + 16 * 64);
            LDS128(A11[0], A11[1], A11[2], A11[3], aP + 24 * 64);
#pragma unroll
            for (int ks = 0; ks < 4; ++ks) {
                const uint32_t kb = (uint32_t)ks * 32;
                uint32_t b00, b01, b10, b11, b20, b21;
                LDSM4(b00, b01, b10, b11, bufB + SWZ(bRowOff01 + kb));
                LDSM2(b20, b21, bufB + SWZ(bRowOff2 + kb));

                const uint32_t a00 = h2lo(A00[ks]);
                const uint32_t a02 = h2hi(A00[ks]);
                const uint32_t a01 = h2lo(A01[ks]);
                const uint32_t a03 = h2hi(A01[ks]);
                const uint32_t a10 = h2lo(A10[ks]);
                const uint32_t a12 = h2hi(A10[ks]);
                const uint32_t a11 = h2lo(A11[ks]);
                const uint32_t a13 = h2hi(A11[ks]);

                MMA16816(acc[0][0], a00, a01, a02, a03, b00, b01);
                MMA16816(acc[0][1], a00, a01, a02, a03, b10, b11);
                MMA16816(acc[0][2], a00, a01, a02, a03, b20, b21);
                MMA16816(acc[1][0], a10, a11, a12, a13, b00, b01);
                MMA16816(acc[1][1], a10, a11, a12, a13, b10, b11);
                MMA16816(acc[1][2], a10, a11, a12, a13, b20, b21);
            }
        }
    }

    const int c0 = (lid & 3) * 2;
    float* pp = g_part + (size_t)blockIdx.y * (NCH * NPIX);
#pragma unroll
    for (int f = 0; f < 2; ++f) {
        const int row0 = m0 + w * 32 + f * 16 + (lid >> 2);
#pragma unroll
        for (int g = 0; g < 3; ++g) {
#pragma unroll
            for (int k = 0; k < 4; ++k) {
                int c = g * 8 + c0 + (k & 1);
                int row = row0 + ((k >> 1) << 3);
                if (c < NCH) pp[c * NPIX + row] = acc[f][g][k];
            }
        }
    }
}

// ---------------- softmax update ----------------
__global__ void k_update(float* __restrict__ out, int final_it) {
    int i = blockIdx.x * blockDim.x + threadIdx.x;
    if (i >= NPIX) return;
    float ri = g_rowinv[i];
    float* dst = final_it ? out : g_q;

    float L[NCH];
    float m = -1e30f;
#pragma unroll
    for (int c = 0; c < NCH; ++c) {
        float s = g_part[c * NPIX + i] + g_part[(NCH + c) * NPIX + i]
                + g_part[(2 * NCH + c) * NPIX + i] + g_part[(3 * NCH + c) * NPIX + i];
        float l = g_U[c * NPIX + i] + (s * ri) * BSCALE + 2.0f * g_qsf[c * NPIX + i];
        L[c] = l;
        m = fmaxf(m, l);
    }
    float se = 0.f;
#pragma unroll
    for (int c = 0; c < NCH; ++c) { L[c] = __expf(L[c] - m); se += L[c]; }
    float inv = 1.0f / se;
#pragma unroll
    for (int c = 0; c < NCH; ++c) {
        float q = L[c] * inv;
        dst[c * NPIX + i] = q;
        g_qh[c * NPIX + i] = __float2half_rn(q * ri);
    }
}

// ---------------- launch ----------------
extern "C" void kernel_launch(void* const* d_in, const int* in_sizes, int n_in,
                              void* d_out, int out_size) {
    const float* unary = nullptr;
    const float* ref = nullptr;
    const float* kstd = nullptr;
    for (int i = 0; i < n_in; ++i) {
        if (in_sizes[i] == NCH * NPIX) unary = (const float*)d_in[i];
        else if (in_sizes[i] == 3 * NPIX) ref = (const float*)d_in[i];
        else if (in_sizes[i] == 5) kstd = (const float*)d_in[i];
    }

    cudaFuncSetAttribute(k_gemm_mma, cudaFuncAttributeMaxDynamicSharedMemorySize, GEMM_SMEM);

    k_feat<<<(NPIX + 255) / 256, 256>>>(ref, kstd);
    k_K<<<dim3(NPIX / 128, NPIX / 32), 256>>>();
    k_init<<<(NPIX + 255) / 256, 256>>>(unary);

    for (int it = 0; it < 5; ++it) {
        k_conv<<<NCH * STRIPS, 384>>>();
        k_gemm_mma<<<dim3(GTILES, KSPLIT), 256, GEMM_SMEM>>>();
        k_update<<<(NPIX + 255) / 256, 256>>>((float*)d_out, it == 4 ? 1 : 0);
    }
}

// round 12
// speedup vs baseline: 1.2419x; 1.0511x over previous
#include <cuda_runtime.h>
#include <cuda_fp16.h>
#include <math.h>
#include <cstdint>

#define HW      96
#define NPIX    9216
#define NCH     21
#define RAD     35
#define KW      71
#define KSPLIT  4
#define KSLICE  2304          // NPIX / KSPLIT
#define CHUNK   128           // k per pipeline chunk (2 panels of 64)
#define NCHUNK  18            // KSLICE / CHUNK
#define NSTAGE  5
#define A_PANEL 16384         // 256 rows * 64B permuted
#define B_PANEL 4096          // 32 ch * 128B (64 k fp16, swizzled)
#define STAGE_BYTES (2 * A_PANEL + 2 * B_PANEL)  // 40960
#define MTILES  72
#define GTILES  36            // NPIX / 256
#define GEMM_SMEM (NSTAGE * STAGE_BYTES + 1024)
#define STRIPS  6
#define SROWS   16
#define HALO    86
#define TROW    (HW + 2 * RAD)
#define BSCALE  (4.0f / 255.0f)

// ---------------- device scratch ----------------
__device__ unsigned char g_Ku[(size_t)NPIX * NPIX];  // 85 MB u8, fragment-permuted rows
__device__ float  g_feat[5][NPIX];
__device__ float  g_nhalf[NPIX];
__device__ float  g_rowpart[NPIX * MTILES];
__device__ float  g_rowinv[NPIX];
__device__ float  g_U[NCH * NPIX];
__device__ float  g_q[NCH * NPIX];
__device__ __half g_qh[32 * NPIX];
__device__ float  g_part[KSPLIT * NCH * NPIX];
__device__ float  g_qsf[NCH * NPIX];
__device__ float  g_g1d[KW];
__device__ int    g_tick[GTILES];   // zero-init; each launch leaves it zeroed

// ---------------- PTX helpers ----------------
__device__ __forceinline__ uint32_t s2u(const void* p) {
    uint32_t a;
    asm("{ .reg .u64 t; cvta.to.shared.u64 t, %1; cvt.u32.u64 %0, t; }" : "=r"(a) : "l"(p));
    return a;
}
#define SWZ(b) ((b) ^ (((b) >> 3) & 0x70))
#define CP16(dst, src) \
    asm volatile("cp.async.cg.shared.global [%0], [%1], 16;" :: "r"(dst), "l"(src) : "memory")
#define CP_COMMIT() asm volatile("cp.async.commit_group;" ::: "memory")
#define CP_WAIT(n)  asm volatile("cp.async.wait_group %0;" :: "n"(n) : "memory")
#define LDS128(r0, r1, r2, r3, addr) \
    asm volatile("ld.shared.v4.u32 {%0,%1,%2,%3}, [%4];" \
                 : "=r"(r0), "=r"(r1), "=r"(r2), "=r"(r3) : "r"(addr))
#define LDSM4(r0, r1, r2, r3, addr) \
    asm volatile("ldmatrix.sync.aligned.m8n8.x4.shared.b16 {%0,%1,%2,%3}, [%4];" \
                 : "=r"(r0), "=r"(r1), "=r"(r2), "=r"(r3) : "r"(addr))
#define LDSM2(r0, r1, addr) \
    asm volatile("ldmatrix.sync.aligned.m8n8.x2.shared.b16 {%0,%1}, [%2];" \
                 : "=r"(r0), "=r"(r1) : "r"(addr))
#define MMA16816(d, a0, a1, a2, a3, b0, b1) \
    asm volatile("mma.sync.aligned.m16n8k16.row.col.f32.f16.f16.f32 " \
                 "{%0,%1,%2,%3}, {%4,%5,%6,%7}, {%8,%9}, {%0,%1,%2,%3};" \
                 : "+f"((d)[0]), "+f"((d)[1]), "+f"((d)[2]), "+f"((d)[3]) \
                 : "r"(a0), "r"(a1), "r"(a2), "r"(a3), "r"(b0), "r"(b1))

__device__ __forceinline__ uint32_t h2lo(uint32_t w) {
    uint32_t r;
    asm("prmt.b32 %0, %1, 0, 0x4140;" : "=r"(r) : "r"(w));
    r |= 0x64006400u;
    asm("sub.rn.f16x2 %0, %0, %1;" : "+r"(r) : "r"(0x64006400u));
    return r;
}
__device__ __forceinline__ uint32_t h2hi(uint32_t w) {
    uint32_t r;
    asm("prmt.b32 %0, %1, 0, 0x4342;" : "=r"(r) : "r"(w));
    r |= 0x64006400u;
    asm("sub.rn.f16x2 %0, %0, %1;" : "+r"(r) : "r"(0x64006400u));
    return r;
}

// ---------------- setup ----------------
__global__ void k_feat(const float* __restrict__ ref, const float* __restrict__ kstd) {
    if (blockIdx.x == 0 && threadIdx.x == 0) {
        float w[KW]; float s = 0.f;
        for (int t = 0; t < KW; ++t) {
            float d = (float)t - (float)RAD;
            w[t] = expf(-(d * d) / 72.0f); s += w[t];
        }
        float inv = 1.0f / s;
        for (int t = 0; t < KW; ++t) g_g1d[t] = w[t] * inv;
    }
    int i = blockIdx.x * blockDim.x + threadIdx.x;
    if (i >= NPIX) return;
    int y = i / HW, x = i % HW;
    float f0 = (float)y / kstd[0];
    float f1 = (float)x / kstd[1];
    float f2 = ref[0 * NPIX + i] / kstd[2];
    float f3 = ref[1 * NPIX + i] / kstd[3];
    float f4 = ref[2 * NPIX + i] / kstd[4];
    g_feat[0][i] = f0; g_feat[1][i] = f1; g_feat[2][i] = f2;
    g_feat[3][i] = f3; g_feat[4][i] = f4;
    g_nhalf[i] = -0.5f * (f0 * f0 + f1 * f1 + f2 * f2 + f3 * f3 + f4 * f4);
}

// K tile (dot form), stored with fragment permutation inside each 64-col block
__global__ void __launch_bounds__(256) k_K() {
    __shared__ float s_fr[5][32];
    __shared__ float s_fc[5][128];
    __shared__ float s_nr[32];
    __shared__ float s_nc[128];
    const int rowBase = blockIdx.y * 32;
    const int colBase = blockIdx.x * 128;
    const int tid = threadIdx.x;

    if (tid < 5 * 32) { int d = tid / 32, rr = tid % 32; s_fr[d][rr] = g_feat[d][rowBase + rr]; }
    if (tid < 32) s_nr[tid] = g_nhalf[rowBase + tid];
    for (int idx = tid; idx < 5 * 128; idx += 256) {
        int d = idx / 128, cc = idx % 128;
        s_fc[d][cc] = g_feat[d][colBase + cc];
    }
    if (tid < 128) s_nc[tid] = g_nhalf[colBase + tid];
    __syncthreads();

    const int r = tid >> 5;
    const int cl = tid & 31;

    float fr[4][5], fc[4][5], nr[4], nc[4];
#pragma unroll
    for (int a = 0; a < 4; ++a) {
#pragma unroll
        for (int d = 0; d < 5; ++d) fr[a][d] = s_fr[d][r * 4 + a];
        nr[a] = s_nr[r * 4 + a];
    }
#pragma unroll
    for (int b = 0; b < 4; ++b) {
#pragma unroll
        for (int d = 0; d < 5; ++d) fc[b][d] = s_fc[d][cl + 32 * b];
        nc[b] = s_nc[cl + 32 * b];
    }

#pragma unroll
    for (int a = 0; a < 4; ++a) {
        const int row = rowBase + r * 4 + a;
        const size_t rowOff = (size_t)row * NPIX;
        float rs = 0.f;
#pragma unroll
        for (int b = 0; b < 4; ++b) {
            float dot = nr[a] + nc[b];
#pragma unroll
            for (int d = 0; d < 5; ++d) dot = fmaf(fr[a][d], fc[b][d], dot);
            float v = __expf(dot);
            rs += v;
            int col = colBase + cl + 32 * b;
            int j = col & 63;
            int s = ((j & 6) << 3) | (((j >> 4) & 3) << 2) | (((j >> 3) & 1) << 1) | (j & 1);
            g_Ku[rowOff + (size_t)(col & ~63) + s] =
                (unsigned char)__float2uint_rn(v * 255.0f);
        }
#pragma unroll
        for (int o = 16; o; o >>= 1) rs += __shfl_xor_sync(0xffffffffu, rs, o);
        if (cl == 0) g_rowpart[row * MTILES + blockIdx.x] = rs;
    }
}

__global__ void k_init(const float* __restrict__ unary) {
    int i = blockIdx.x * blockDim.x + threadIdx.x;
    if (i >= NPIX) return;
    float s = 0.f;
    const float* p = g_rowpart + i * MTILES;
#pragma unroll
    for (int b = 0; b < MTILES; ++b) s += p[b];
    float ri = 1.0f / (sqrtf(s) + 1e-8f);
    g_rowinv[i] = ri;

    float L[NCH];
    float m = -1e30f;
#pragma unroll
    for (int c = 0; c < NCH; ++c) {
        float u = unary[c * NPIX + i];
        u = fminf(fmaxf(u, 1e-5f), 1.0f);
        float lu = logf(u);
        g_U[c * NPIX + i] = lu;
        L[c] = lu;
        m = fmaxf(m, lu);
    }
    float se = 0.f;
#pragma unroll
    for (int c = 0; c < NCH; ++c) { L[c] = __expf(L[c] - m); se += L[c]; }
    float inv = 1.0f / se;
#pragma unroll
    for (int c = 0; c < NCH; ++c) {
        float q = L[c] * inv;
        g_q[c * NPIX + i] = q;
        g_qh[c * NPIX + i] = __float2half_rn(q * ri);
    }
#pragma unroll
    for (int c = NCH; c < 32; ++c) g_qh[c * NPIX + i] = __float2half_rn(0.f);
}

// ---------------- strip-parallel separable conv, tap-major ----------------
__global__ void __launch_bounds__(384) k_conv() {
    __shared__ float sImg[HALO * HW];
    __shared__ float sTmp[SROWS * TROW];
    __shared__ float sW[KW];
    const int c = blockIdx.x / STRIPS;
    const int strip = blockIdx.x % STRIPS;
    const int y0 = strip * SROWS;
    const int rowLo = y0 - RAD;
    const int tid = threadIdx.x;

    if (tid < KW) sW[tid] = g_g1d[tid];
    const float* src = g_q + c * NPIX;
    for (int p = tid; p < HALO * HW; p += 384) {
        int r = p / HW, x = p - r * HW;
        int gr = rowLo + r;
        sImg[p] = (gr >= 0 && gr < HW) ? src[gr * HW + x] : 0.f;
    }
    for (int p = tid; p < SROWS * TROW; p += 384) sTmp[p] = 0.f;
    __syncthreads();

    // Y pass, tap-major: px j at p_j = tid + 384j; sImg index = p_j + t*HW
    {
        float a0 = 0.f, a1 = 0.f, a2 = 0.f, a3 = 0.f;
        const int p0 = tid, p1 = tid + 384, p2 = tid + 768, p3 = tid + 1152;
#pragma unroll
        for (int t = 0; t < KW; ++t) {
            const float wv = sW[t];
            const int o = t * HW;
            a0 = fmaf(wv, sImg[p0 + o], a0);
            a1 = fmaf(wv, sImg[p1 + o], a1);
            a2 = fmaf(wv, sImg[p2 + o], a2);
            a3 = fmaf(wv, sImg[p3 + o], a3);
        }
        int y, x;
        y = p0 / HW; x = p0 - y * HW; sTmp[y * TROW + RAD + x] = a0;
        y = p1 / HW; x = p1 - y * HW; sTmp[y * TROW + RAD + x] = a1;
        y = p2 / HW; x = p2 - y * HW; sTmp[y * TROW + RAD + x] = a2;
        y = p3 / HW; x = p3 - y * HW; sTmp[y * TROW + RAD + x] = a3;
    }
    __syncthreads();

    // X pass, tap-major: sTmp index = yy*TROW + x + t
    {
        float a0 = 0.f, a1 = 0.f, a2 = 0.f, a3 = 0.f;
        const int p0 = tid, p1 = tid + 384, p2 = tid + 768, p3 = tid + 1152;
        int y, x;
        y = p0 / HW; x = p0 - y * HW; const int b0 = y * TROW + x;
        y = p1 / HW; x = p1 - y * HW; const int b1 = y * TROW + x;
        y = p2 / HW; x = p2 - y * HW; const int b2 = y * TROW + x;
        y = p3 / HW; x = p3 - y * HW; const int b3 = y * TROW + x;
#pragma unroll
        for (int t = 0; t < KW; ++t) {
            const float wv = sW[t];
            a0 = fmaf(wv, sTmp[b0 + t], a0);
            a1 = fmaf(wv, sTmp[b1 + t], a1);
            a2 = fmaf(wv, sTmp[b2 + t], a2);
            a3 = fmaf(wv, sTmp[b3 + t], a3);
        }
        float* dst = g_qsf + c * NPIX + y0 * HW;
        dst[p0] = a0; dst[p1] = a1; dst[p2] = a2; dst[p3] = a3;
    }
}

// ---------------- u8-A HMMA GEMM + fused last-block softmax update ----------------
__global__ void __launch_bounds__(256, 1) k_gemm_mma(float* __restrict__ out, int final_it) {
    extern __shared__ char dynRaw[];
    __shared__ int sLast;
    const uint32_t dynb = (s2u(dynRaw) + 1023u) & ~1023u;
    const int tid = threadIdx.x, w = tid >> 5, lid = tid & 31;
    const int m0 = blockIdx.x * 256;
    const int zbase = blockIdx.y * KSLICE;

    const unsigned char* Abase = g_Ku + (size_t)m0 * NPIX + zbase;
    const __half* Bbase = g_qh + zbase;

    auto load_chunk = [&](int ci) {
        const uint32_t stage = dynb + (uint32_t)(ci % NSTAGE) * STAGE_BYTES;
        const int koff = ci * CHUNK;
#pragma unroll
        for (int u = tid; u < 2560; u += 256) {
            uint32_t dst; const void* src;
            if (u < 2048) {
                int r = u >> 3, t = u & 7;
                src = Abase + (size_t)r * NPIX + koff + t * 16;
                dst = stage + (uint32_t)((t >> 2) * A_PANEL + r * 64 + (t & 3) * 16);
            } else {
                int v = u - 2048;
                int pl = v >> 8, cc = (v >> 3) & 31, t = v & 7;
                src = Bbase + (size_t)cc * NPIX + koff + pl * 64 + t * 8;
                dst = stage + 2 * A_PANEL + (uint32_t)pl * B_PANEL
                    + SWZ((uint32_t)(cc * 128 + t * 16));
            }
            CP16(dst, src);
        }
        CP_COMMIT();
    };

    float acc[2][3][4];
#pragma unroll
    for (int f = 0; f < 2; ++f)
#pragma unroll
        for (int g = 0; g < 3; ++g)
#pragma unroll
            for (int k = 0; k < 4; ++k) acc[f][g][k] = 0.f;

    for (int i = 0; i < NSTAGE - 1; ++i) load_chunk(i);

    const uint32_t aBase = (uint32_t)((w * 32 + (lid >> 2)) * 64 + (lid & 3) * 16);
    const uint32_t bRowOff01 = (uint32_t)(((lid & 7) + ((lid >> 4) << 3)) * 128) + (((lid >> 3) & 1) << 4);
    const uint32_t bRowOff2 = (uint32_t)((16 + (lid & 7)) * 128) + (((lid >> 3) & 1) << 4);

    for (int i = 0; i < NCHUNK; ++i) {
        if (i + NSTAGE - 1 < NCHUNK) CP_WAIT(NSTAGE - 2); else CP_WAIT(0);
        __syncthreads();
        if (i + NSTAGE - 1 < NCHUNK) load_chunk(i + NSTAGE - 1);

        const uint32_t stage = dynb + (uint32_t)(i % NSTAGE) * STAGE_BYTES;
#pragma unroll
        for (int pl = 0; pl < 2; ++pl) {
            const uint32_t aP = stage + (uint32_t)pl * A_PANEL + aBase;
            const uint32_t bufB = stage + 2 * A_PANEL + (uint32_t)pl * B_PANEL;
            uint32_t A00[4], A01[4], A10[4], A11[4];
            LDS128(A00[0], A00[1], A00[2], A00[3], aP);
            LDS128(A01[0], A01[1], A01[2], A01[3], aP + 8 * 64);
            LDS128(A10[0], A10[1], A10[2], A10[3], aP + 16 * 64);
            LDS128(A11[0], A11[1], A11[2], A11[3], aP + 24 * 64);
#pragma unroll
            for (int ks = 0; ks < 4; ++ks) {
                const uint32_t kb = (uint32_t)ks * 32;
                uint32_t b00, b01, b10, b11, b20, b21;
                LDSM4(b00, b01, b10, b11, bufB + SWZ(bRowOff01 + kb));
                LDSM2(b20, b21, bufB + SWZ(bRowOff2 + kb));

                const uint32_t a00 = h2lo(A00[ks]);
                const uint32_t a02 = h2hi(A00[ks]);
                const uint32_t a01 = h2lo(A01[ks]);
                const uint32_t a03 = h2hi(A01[ks]);
                const uint32_t a10 = h2lo(A10[ks]);
                const uint32_t a12 = h2hi(A10[ks]);
                const uint32_t a11 = h2lo(A11[ks]);
                const uint32_t a13 = h2hi(A11[ks]);

                MMA16816(acc[0][0], a00, a01, a02, a03, b00, b01);
                MMA16816(acc[0][1], a00, a01, a02, a03, b10, b11);
                MMA16816(acc[0][2], a00, a01, a02, a03, b20, b21);
                MMA16816(acc[1][0], a10, a11, a12, a13, b00, b01);
                MMA16816(acc[1][1], a10, a11, a12, a13, b10, b11);
                MMA16816(acc[1][2], a10, a11, a12, a13, b20, b21);
            }
        }
    }

    const int c0 = (lid & 3) * 2;
    float* pp = g_part + (size_t)blockIdx.y * (NCH * NPIX);
#pragma unroll
    for (int f = 0; f < 2; ++f) {
        const int row0 = m0 + w * 32 + f * 16 + (lid >> 2);
#pragma unroll
        for (int g = 0; g < 3; ++g) {
#pragma unroll
            for (int k = 0; k < 4; ++k) {
                int c = g * 8 + c0 + (k & 1);
                int row = row0 + ((k >> 1) << 3);
                if (c < NCH) pp[c * NPIX + row] = acc[f][g][k];
            }
        }
    }

    // ---- last-block ticket: 4th arriver does the softmax update for 256 px ----
    __threadfence();
    __syncthreads();
    if (tid == 0) {
        int old = atomicAdd(&g_tick[blockIdx.x], 1);
        sLast = (old == KSPLIT - 1) ? 1 : 0;
    }
    __syncthreads();
    if (sLast) {
        __threadfence();
        const int i = m0 + tid;   // 256 threads, 256 rows
        const float ri = g_rowinv[i];
        float L[NCH];
        float m = -1e30f;
#pragma unroll
        for (int c = 0; c < NCH; ++c) {
            float s = g_part[c * NPIX + i] + g_part[(NCH + c) * NPIX + i]
                    + g_part[(2 * NCH + c) * NPIX + i] + g_part[(3 * NCH + c) * NPIX + i];
            float l = g_U[c * NPIX + i] + (s * ri) * BSCALE + 2.0f * g_qsf[c * NPIX + i];
            L[c] = l;
            m = fmaxf(m, l);
        }
        float se = 0.f;
#pragma unroll
        for (int c = 0; c < NCH; ++c) { L[c] = __expf(L[c] - m); se += L[c]; }
        float inv = 1.0f / se;
#pragma unroll
        for (int c = 0; c < NCH; ++c) {
            float q = L[c] * inv;
            g_q[c * NPIX + i] = q;
            g_qh[c * NPIX + i] = __float2half_rn(q * ri);
            if (final_it) out[c * NPIX + i] = q;
        }
        if (tid == 0) g_tick[blockIdx.x] = 0;   // re-arm for next launch/replay
    }
}

// ---------------- launch ----------------
extern "C" void kernel_launch(void* const* d_in, const int* in_sizes, int n_in,
                              void* d_out, int out_size) {
    const float* unary = nullptr;
    const float* ref = nullptr;
    const float* kstd = nullptr;
    for (int i = 0; i < n_in; ++i) {
        if (in_sizes[i] == NCH * NPIX) unary = (const float*)d_in[i];
        else if (in_sizes[i] == 3 * NPIX) ref = (const float*)d_in[i];
        else if (in_sizes[i] == 5) kstd = (const float*)d_in[i];
    }

    cudaFuncSetAttribute(k_gemm_mma, cudaFuncAttributeMaxDynamicSharedMemorySize, GEMM_SMEM);

    k_feat<<<(NPIX + 255) / 256, 256>>>(ref, kstd);
    k_K<<<dim3(NPIX / 128, NPIX / 32), 256>>>();
    k_init<<<(NPIX + 255) / 256, 256>>>(unary);

    for (int it = 0; it < 5; ++it) {
        k_conv<<<NCH * STRIPS, 384>>>();
        k_gemm_mma<<<dim3(GTILES, KSPLIT), 256, GEMM_SMEM>>>((float*)d_out, it == 4 ? 1 : 0);
    }
}

// round 13
// speedup vs baseline: 1.4318x; 1.1530x over previous
#include <cuda_runtime.h>
#include <cuda_fp16.h>
#include <math.h>
#include <cstdint>

#define HW      96
#define NPIX    9216
#define NCH     21
#define RAD     35
#define KW      71
#define KSPLIT  4
#define KSLICE  2304          // NPIX / KSPLIT
#define CHUNK   128           // k per pipeline chunk (2 panels of 64)
#define NCHUNK  18            // KSLICE / CHUNK
#define NSTAGE  4
#define A_STRIDE 144
#define A_PANEL (256 * A_STRIDE)   // 36864
#define B_PANEL 4096
#define STAGE_BYTES (A_PANEL + 2 * B_PANEL)  // 45056
#define RP      72            // rowpart slots (128-col tiles)
#define GTILES  36            // NPIX / 256
#define GEMM_SMEM (NSTAGE * STAGE_BYTES + 1024)
#define STRIPS  6
#define SROWS   16
#define HALO    86
#define TROW    (HW + 2 * RAD)
#define BSCALE  (4.0f / 255.0f)

// ---------------- device scratch ----------------
__device__ unsigned char g_Ku[(size_t)NPIX * NPIX];  // 85 MB u8, plain layout
__device__ float  g_feat[5][NPIX];
__device__ float  g_nhalf[NPIX];
__device__ float  g_rowpart[NPIX * RP];
__device__ float  g_rowinv[NPIX];
__device__ float  g_U[NCH * NPIX];
__device__ float  g_q[NCH * NPIX];
__device__ __half g_qh[32 * NPIX];
__device__ float  g_part[KSPLIT * NCH * NPIX];
__device__ float  g_qsf[NCH * NPIX];
__device__ float  g_g1d[KW];
__device__ int    g_tick[GTILES];

// ---------------- PTX helpers ----------------
__device__ __forceinline__ uint32_t s2u(const void* p) {
    uint32_t a;
    asm("{ .reg .u64 t; cvta.to.shared.u64 t, %1; cvt.u32.u64 %0, t; }" : "=r"(a) : "l"(p));
    return a;
}
#define SWZ(b) ((b) ^ (((b) >> 3) & 0x70))
#define CP16(dst, src) \
    asm volatile("cp.async.cg.shared.global [%0], [%1], 16;" :: "r"(dst), "l"(src) : "memory")
#define CP_COMMIT() asm volatile("cp.async.commit_group;" ::: "memory")
#define CP_WAIT(n)  asm volatile("cp.async.wait_group %0;" :: "n"(n) : "memory")
#define LDSU16(r, addr) \
    asm volatile("ld.shared.u16 %0, [%1];" : "=r"(r) : "r"(addr))
#define LDSM4(r0, r1, r2, r3, addr) \
    asm volatile("ldmatrix.sync.aligned.m8n8.x4.shared.b16 {%0,%1,%2,%3}, [%4];" \
                 : "=r"(r0), "=r"(r1), "=r"(r2), "=r"(r3) : "r"(addr))
#define LDSM2(r0, r1, addr) \
    asm volatile("ldmatrix.sync.aligned.m8n8.x2.shared.b16 {%0,%1}, [%2];" \
                 : "=r"(r0), "=r"(r1) : "r"(addr))
#define MMA16816(d, a0, a1, a2, a3, b0, b1) \
    asm volatile("mma.sync.aligned.m16n8k16.row.col.f32.f16.f16.f32 " \
                 "{%0,%1,%2,%3}, {%4,%5,%6,%7}, {%8,%9}, {%0,%1,%2,%3};" \
                 : "+f"((d)[0]), "+f"((d)[1]), "+f"((d)[2]), "+f"((d)[3]) \
                 : "r"(a0), "r"(a1), "r"(a2), "r"(a3), "r"(b0), "r"(b1))

__device__ __forceinline__ uint32_t u8x2_to_h2(uint32_t w) {
    uint32_t r;
    asm("prmt.b32 %0, %1, 0, 0x4140;" : "=r"(r) : "r"(w));
    r |= 0x64006400u;
    asm("sub.rn.f16x2 %0, %0, %1;" : "+r"(r) : "r"(0x64006400u));
    return r;
}

// ---------------- setup ----------------
__global__ void k_feat(const float* __restrict__ ref, const float* __restrict__ kstd) {
    if (blockIdx.x == 0 && threadIdx.x == 0) {
        float w[KW]; float s = 0.f;
        for (int t = 0; t < KW; ++t) {
            float d = (float)t - (float)RAD;
            w[t] = expf(-(d * d) / 72.0f); s += w[t];
        }
        float inv = 1.0f / s;
        for (int t = 0; t < KW; ++t) g_g1d[t] = w[t] * inv;
    }
    int i = blockIdx.x * blockDim.x + threadIdx.x;
    if (i >= NPIX) return;
    int y = i / HW, x = i % HW;
    float f0 = (float)y / kstd[0];
    float f1 = (float)x / kstd[1];
    float f2 = ref[0 * NPIX + i] / kstd[2];
    float f3 = ref[1 * NPIX + i] / kstd[3];
    float f4 = ref[2 * NPIX + i] / kstd[4];
    g_feat[0][i] = f0; g_feat[1][i] = f1; g_feat[2][i] = f2;
    g_feat[3][i] = f3; g_feat[4][i] = f4;
    g_nhalf[i] = -0.5f * (f0 * f0 + f1 * f1 + f2 * f2 + f3 * f3 + f4 * f4);
}

// ---------------- symmetric K: upper-triangle 128x128 tiles ----------------
// grid (72, 72); blocks with a > b exit. Block computes tile (a,b), stages in
// smem, writes tile AND (a!=b) its transpose, coalesced u32. Row partials for
// rows of a (slot b) and rows of b (slot a) via deterministic 2-phase reduce.
__global__ void __launch_bounds__(256) k_K() {
    const int a = blockIdx.y, b = blockIdx.x;
    if (a > b) return;
    __shared__ float fA[5][128], fB[5][128], nA[128], nB[128];
    __shared__ unsigned char sT[128 * 132];      // padded rows
    __shared__ float redR[16][128], redC[16][128];
    const int tid = threadIdx.x;
    const int tr = tid >> 4, tc = tid & 15;

    if (tid < 128) {
#pragma unroll
        for (int d = 0; d < 5; ++d) {
            fA[d][tid] = g_feat[d][a * 128 + tid];
            fB[d][tid] = g_feat[d][b * 128 + tid];
        }
        nA[tid] = g_nhalf[a * 128 + tid];
        nB[tid] = g_nhalf[b * 128 + tid];
    }
    __syncthreads();

    float rf[5][8], nri[8];
#pragma unroll
    for (int i = 0; i < 8; ++i) {
#pragma unroll
        for (int d = 0; d < 5; ++d) rf[d][i] = fA[d][tr * 8 + i];
        nri[i] = nA[tr * 8 + i];
    }

    float rs[8];
#pragma unroll
    for (int i = 0; i < 8; ++i) rs[i] = 0.f;

#pragma unroll
    for (int jj = 0; jj < 8; ++jj) {
        const int c = tc * 8 + jj;
        const float c0 = fB[0][c], c1 = fB[1][c], c2 = fB[2][c],
                    c3 = fB[3][c], c4 = fB[4][c];
        const float ncj = nB[c];
        float cs = 0.f;
#pragma unroll
        for (int i = 0; i < 8; ++i) {
            float dot = nri[i] + ncj;
            dot = fmaf(rf[0][i], c0, dot);
            dot = fmaf(rf[1][i], c1, dot);
            dot = fmaf(rf[2][i], c2, dot);
            dot = fmaf(rf[3][i], c3, dot);
            dot = fmaf(rf[4][i], c4, dot);
            float v = __expf(dot);
            rs[i] += v;
            cs += v;
            sT[(tr * 8 + i) * 132 + c] = (unsigned char)__float2uint_rn(v * 255.0f);
        }
        redC[tr][c] = cs;
    }
#pragma unroll
    for (int i = 0; i < 8; ++i) redR[tc][tr * 8 + i] = rs[i];
    __syncthreads();

    if (tid < 128) {
        float sR = 0.f, sC = 0.f;
#pragma unroll
        for (int k = 0; k < 16; ++k) { sR += redR[k][tid]; sC += redC[k][tid]; }
        g_rowpart[(a * 128 + tid) * RP + b] = sR;
        if (a != b) g_rowpart[(b * 128 + tid) * RP + a] = sC;
    }

    // normal tile write: 4096 u32 words, warp = one 128B row
    for (int wid = tid; wid < 4096; wid += 256) {
        const int r = wid >> 5, wc = wid & 31;
        uint32_t v = *(const uint32_t*)(sT + r * 132 + wc * 4);
        *(uint32_t*)(g_Ku + (size_t)(a * 128 + r) * NPIX + b * 128 + wc * 4) = v;
    }
    if (a != b) {
        for (int wid = tid; wid < 4096; wid += 256) {
            const int c = wid >> 5, wr = wid & 31;
            uint32_t b0 = sT[(wr * 4 + 0) * 132 + c];
            uint32_t b1 = sT[(wr * 4 + 1) * 132 + c];
            uint32_t b2 = sT[(wr * 4 + 2) * 132 + c];
            uint32_t b3 = sT[(wr * 4 + 3) * 132 + c];
            uint32_t v = b0 | (b1 << 8) | (b2 << 16) | (b3 << 24);
            *(uint32_t*)(g_Ku + (size_t)(b * 128 + c) * NPIX + a * 128 + wr * 4) = v;
        }
    }
}

__global__ void k_init(const float* __restrict__ unary) {
    int i = blockIdx.x * blockDim.x + threadIdx.x;
    if (i >= NPIX) return;
    float s = 0.f;
    const float* p = g_rowpart + i * RP;
#pragma unroll
    for (int bq = 0; bq < RP; ++bq) s += p[bq];
    float ri = 1.0f / (sqrtf(s) + 1e-8f);
    g_rowinv[i] = ri;

    float L[NCH];
    float m = -1e30f;
#pragma unroll
    for (int c = 0; c < NCH; ++c) {
        float u = unary[c * NPIX + i];
        u = fminf(fmaxf(u, 1e-5f), 1.0f);
        float lu = logf(u);
        g_U[c * NPIX + i] = lu;
        L[c] = lu;
        m = fmaxf(m, lu);
    }
    float se = 0.f;
#pragma unroll
    for (int c = 0; c < NCH; ++c) { L[c] = __expf(L[c] - m); se += L[c]; }
    float inv = 1.0f / se;
#pragma unroll
    for (int c = 0; c < NCH; ++c) {
        float q = L[c] * inv;
        g_q[c * NPIX + i] = q;
        g_qh[c * NPIX + i] = __float2half_rn(q * ri);
    }
#pragma unroll
    for (int c = NCH; c < 32; ++c) g_qh[c * NPIX + i] = __float2half_rn(0.f);
}

// ---------------- strip-parallel separable conv, tap-major ----------------
__global__ void __launch_bounds__(384) k_conv() {
    __shared__ float sImg[HALO * HW];
    __shared__ float sTmp[SROWS * TROW];
    __shared__ float sW[KW];
    const int c = blockIdx.x / STRIPS;
    const int strip = blockIdx.x % STRIPS;
    const int y0 = strip * SROWS;
    const int rowLo = y0 - RAD;
    const int tid = threadIdx.x;

    if (tid < KW) sW[tid] = g_g1d[tid];
    const float* src = g_q + c * NPIX;
    for (int p = tid; p < HALO * HW; p += 384) {
        int r = p / HW, x = p - r * HW;
        int gr = rowLo + r;
        sImg[p] = (gr >= 0 && gr < HW) ? src[gr * HW + x] : 0.f;
    }
    for (int p = tid; p < SROWS * TROW; p += 384) sTmp[p] = 0.f;
    __syncthreads();

    {
        float a0 = 0.f, a1 = 0.f, a2 = 0.f, a3 = 0.f;
        const int p0 = tid, p1 = tid + 384, p2 = tid + 768, p3 = tid + 1152;
#pragma unroll
        for (int t = 0; t < KW; ++t) {
            const float wv = sW[t];
            const int o = t * HW;
            a0 = fmaf(wv, sImg[p0 + o], a0);
            a1 = fmaf(wv, sImg[p1 + o], a1);
            a2 = fmaf(wv, sImg[p2 + o], a2);
            a3 = fmaf(wv, sImg[p3 + o], a3);
        }
        int y, x;
        y = p0 / HW; x = p0 - y * HW; sTmp[y * TROW + RAD + x] = a0;
        y = p1 / HW; x = p1 - y * HW; sTmp[y * TROW + RAD + x] = a1;
        y = p2 / HW; x = p2 - y * HW; sTmp[y * TROW + RAD + x] = a2;
        y = p3 / HW; x = p3 - y * HW; sTmp[y * TROW + RAD + x] = a3;
    }
    __syncthreads();

    {
        float a0 = 0.f, a1 = 0.f, a2 = 0.f, a3 = 0.f;
        const int p0 = tid, p1 = tid + 384, p2 = tid + 768, p3 = tid + 1152;
        int y, x;
        y = p0 / HW; x = p0 - y * HW; const int b0 = y * TROW + x;
        y = p1 / HW; x = p1 - y * HW; const int b1 = y * TROW + x;
        y = p2 / HW; x = p2 - y * HW; const int b2 = y * TROW + x;
        y = p3 / HW; x = p3 - y * HW; const int b3 = y * TROW + x;
#pragma unroll
        for (int t = 0; t < KW; ++t) {
            const float wv = sW[t];
            a0 = fmaf(wv, sTmp[b0 + t], a0);
            a1 = fmaf(wv, sTmp[b1 + t], a1);
            a2 = fmaf(wv, sTmp[b2 + t], a2);
            a3 = fmaf(wv, sTmp[b3 + t], a3);
        }
        float* dst = g_qsf + c * NPIX + y0 * HW;
        dst[p0] = a0; dst[p1] = a1; dst[p2] = a2; dst[p3] = a3;
    }
}

// ---------------- u8-A HMMA GEMM + fused last-block softmax update ----------------
__global__ void __launch_bounds__(256, 1) k_gemm_mma(float* __restrict__ out, int final_it) {
    extern __shared__ char dynRaw[];
    __shared__ int sLast;
    const uint32_t dynb = (s2u(dynRaw) + 1023u) & ~1023u;
    const int tid = threadIdx.x, w = tid >> 5, lid = tid & 31;
    const int m0 = blockIdx.x * 256;
    const int zbase = blockIdx.y * KSLICE;

    const unsigned char* Abase = g_Ku + (size_t)m0 * NPIX + zbase;
    const __half* Bbase = g_qh + zbase;

    auto load_chunk = [&](int ci) {
        const uint32_t stage = dynb + (uint32_t)(ci % NSTAGE) * STAGE_BYTES;
        const int koff = ci * CHUNK;
#pragma unroll
        for (int u = tid; u < 2560; u += 256) {
            uint32_t dst; const void* src;
            if (u < 2048) {                 // A: 256 rows x 128B (u8)
                int r = u >> 3, t = u & 7;
                src = Abase + (size_t)r * NPIX + koff + t * 16;
                dst = stage + (uint32_t)(r * A_STRIDE + t * 16);
            } else {                        // B: 2 panels x 32 ch x 128B
                int v = u - 2048;
                int pl = v >> 8, cc = (v >> 3) & 31, t = v & 7;
                src = Bbase + (size_t)cc * NPIX + koff + pl * 64 + t * 8;
                dst = stage + A_PANEL + (uint32_t)pl * B_PANEL
                    + SWZ((uint32_t)(cc * 128 + t * 16));
            }
            CP16(dst, src);
        }
        CP_COMMIT();
    };

    float acc[2][3][4];
#pragma unroll
    for (int f = 0; f < 2; ++f)
#pragma unroll
        for (int g = 0; g < 3; ++g)
#pragma unroll
            for (int k = 0; k < 4; ++k) acc[f][g][k] = 0.f;

    for (int i = 0; i < NSTAGE - 1; ++i) load_chunk(i);

    const uint32_t aBase0 = (uint32_t)((w * 32 + (lid >> 2)) * A_STRIDE + (lid & 3) * 2);
    const uint32_t aBase1 = aBase0 + 16 * A_STRIDE;
    const uint32_t bRowOff01 = (uint32_t)(((lid & 7) + ((lid >> 4) << 3)) * 128) + (((lid >> 3) & 1) << 4);
    const uint32_t bRowOff2 = (uint32_t)((16 + (lid & 7)) * 128) + (((lid >> 3) & 1) << 4);

    for (int i = 0; i < NCHUNK; ++i) {
        if (i + NSTAGE - 1 < NCHUNK) CP_WAIT(NSTAGE - 2); else CP_WAIT(0);
        __syncthreads();
        if (i + NSTAGE - 1 < NCHUNK) load_chunk(i + NSTAGE - 1);

        const uint32_t stage = dynb + (uint32_t)(i % NSTAGE) * STAGE_BYTES;
#pragma unroll
        for (int pl = 0; pl < 2; ++pl) {
            const uint32_t aOff = stage + (uint32_t)pl * 64;
            const uint32_t bufB = stage + A_PANEL + (uint32_t)pl * B_PANEL;
#pragma unroll
            for (int ks = 0; ks < 4; ++ks) {
                const uint32_t kb = (uint32_t)ks * 32;
                uint32_t b00, b01, b10, b11, b20, b21;
                LDSM4(b00, b01, b10, b11, bufB + SWZ(bRowOff01 + kb));
                LDSM2(b20, b21, bufB + SWZ(bRowOff2 + kb));

                const uint32_t ad0 = aOff + aBase0 + (uint32_t)ks * 16;
                const uint32_t ad1 = aOff + aBase1 + (uint32_t)ks * 16;
                uint32_t w0, w1, w2, w3, w4, w5, w6, w7;
                LDSU16(w0, ad0);
                LDSU16(w1, ad0 + 8 * A_STRIDE);
                LDSU16(w2, ad0 + 8);
                LDSU16(w3, ad0 + 8 * A_STRIDE + 8);
                LDSU16(w4, ad1);
                LDSU16(w5, ad1 + 8 * A_STRIDE);
                LDSU16(w6, ad1 + 8);
                LDSU16(w7, ad1 + 8 * A_STRIDE + 8);
                const uint32_t a00 = u8x2_to_h2(w0);
                const uint32_t a01 = u8x2_to_h2(w1);
                const uint32_t a02 = u8x2_to_h2(w2);
                const uint32_t a03 = u8x2_to_h2(w3);
                const uint32_t a10 = u8x2_to_h2(w4);
                const uint32_t a11 = u8x2_to_h2(w5);
                const uint32_t a12 = u8x2_to_h2(w6);
                const uint32_t a13 = u8x2_to_h2(w7);

                MMA16816(acc[0][0], a00, a01, a02, a03, b00, b01);
                MMA16816(acc[0][1], a00, a01, a02, a03, b10, b11);
                MMA16816(acc[0][2], a00, a01, a02, a03, b20, b21);
                MMA16816(acc[1][0], a10, a11, a12, a13, b00, b01);
                MMA16816(acc[1][1], a10, a11, a12, a13, b10, b11);
                MMA16816(acc[1][2], a10, a11, a12, a13, b20, b21);
            }
        }
    }

    const int c0 = (lid & 3) * 2;
    float* pp = g_part + (size_t)blockIdx.y * (NCH * NPIX);
#pragma unroll
    for (int f = 0; f < 2; ++f) {
        const int row0 = m0 + w * 32 + f * 16 + (lid >> 2);
#pragma unroll
        for (int g = 0; g < 3; ++g) {
#pragma unroll
            for (int k = 0; k < 4; ++k) {
                int c = g * 8 + c0 + (k & 1);
                int row = row0 + ((k >> 1) << 3);
                if (c < NCH) pp[c * NPIX + row] = acc[f][g][k];
            }
        }
    }

    __threadfence();
    __syncthreads();
    if (tid == 0) {
        int old = atomicAdd(&g_tick[blockIdx.x], 1);
        sLast = (old == KSPLIT - 1) ? 1 : 0;
    }
    __syncthreads();
    if (sLast) {
        __threadfence();
        const int i = m0 + tid;
        const float ri = g_rowinv[i];
        float L[NCH];
        float m = -1e30f;
#pragma unroll
        for (int c = 0; c < NCH; ++c) {
            float s = g_part[c * NPIX + i] + g_part[(NCH + c) * NPIX + i]
                    + g_part[(2 * NCH + c) * NPIX + i] + g_part[(3 * NCH + c) * NPIX + i];
            float l = g_U[c * NPIX + i] + (s * ri) * BSCALE + 2.0f * g_qsf[c * NPIX + i];
            L[c] = l;
            m = fmaxf(m, l);
        }
        float se = 0.f;
#pragma unroll
        for (int c = 0; c < NCH; ++c) { L[c] = __expf(L[c] - m); se += L[c]; }
        float inv = 1.0f / se;
#pragma unroll
        for (int c = 0; c < NCH; ++c) {
            float q = L[c] * inv;
            g_q[c * NPIX + i] = q;
            g_qh[c * NPIX + i] = __float2half_rn(q * ri);
            if (final_it) out[c * NPIX + i] = q;
        }
        if (tid == 0) g_tick[blockIdx.x] = 0;
    }
}

// ---------------- launch ----------------
extern "C" void kernel_launch(void* const* d_in, const int* in_sizes, int n_in,
                              void* d_out, int out_size) {
    const float* unary = nullptr;
    const float* ref = nullptr;
    const float* kstd = nullptr;
    for (int i = 0; i < n_in; ++i) {
        if (in_sizes[i] == NCH * NPIX) unary = (const float*)d_in[i];
        else if (in_sizes[i] == 3 * NPIX) ref = (const float*)d_in[i];
        else if (in_sizes[i] == 5) kstd = (const float*)d_in[i];
    }

    cudaFuncSetAttribute(k_gemm_mma, cudaFuncAttributeMaxDynamicSharedMemorySize, GEMM_SMEM);

    k_feat<<<(NPIX + 255) / 256, 256>>>(ref, kstd);
    k_K<<<dim3(RP, RP), 256>>>();
    k_init<<<(NPIX + 255) / 256, 256>>>(unary);

    for (int it = 0; it < 5; ++it) {
        k_conv<<<NCH * STRIPS, 384>>>();
        k_gemm_mma<<<dim3(GTILES, KSPLIT), 256, GEMM_SMEM>>>((float*)d_out, it == 4 ? 1 : 0);
    }
}

// round 14
// speedup vs baseline: 1.5401x; 1.0756x over previous
#include <cuda_runtime.h>
#include <cuda_fp16.h>
#include <math.h>
#include <cstdint>

#define HW      96
#define NPIX    9216
#define NCH     21
#define RAD     35
#define KW      71
#define KSPLIT  4
#define KSLICE  2304
#define CHUNK   128
#define NCHUNK  18
#define NSTAGE  3
#define A_STRIDE 144
#define A_PANEL (256 * A_STRIDE)   // 36864
#define B_PANEL 4096
#define STAGE_BYTES (A_PANEL + 2 * B_PANEL)  // 45056
#define RP      72
#define GTILES  36
#define DYN_SMEM (NSTAGE * STAGE_BYTES + 1024)  // 136192
#define STRIPS  6
#define SROWS   16
#define HALO    86
#define TROW    (HW + 2 * RAD)
#define NCONV   (NCH * STRIPS)     // 126 conv units
#define BSCALE  (4.0f / 255.0f)

// ---------------- device scratch ----------------
__device__ unsigned char g_Ku[(size_t)NPIX * NPIX];
__device__ float  g_feat[5][NPIX];
__device__ float  g_nhalf[NPIX];
__device__ float  g_rowpart[NPIX * RP];
__device__ float  g_rowinv[NPIX];
__device__ float  g_U[NCH * NPIX];
__device__ float  g_q[NCH * NPIX];
__device__ __half g_qh0[32 * NPIX];          // ping-pong B buffers
__device__ __half g_qh1[32 * NPIX];
__device__ float  g_part[KSPLIT * NCH * NPIX];
__device__ float  g_qsf[NCH * NPIX];
__device__ float  g_g1d[KW];
__device__ int    g_tick[GTILES];
__device__ int    g_cnt;                     // conv units completed (this launch seq)

// ---------------- PTX helpers ----------------
__device__ __forceinline__ uint32_t s2u(const void* p) {
    uint32_t a;
    asm("{ .reg .u64 t; cvta.to.shared.u64 t, %1; cvt.u32.u64 %0, t; }" : "=r"(a) : "l"(p));
    return a;
}
#define SWZ(b) ((b) ^ (((b) >> 3) & 0x70))
#define CP16(dst, src) \
    asm volatile("cp.async.cg.shared.global [%0], [%1], 16;" :: "r"(dst), "l"(src) : "memory")
#define CP_COMMIT() asm volatile("cp.async.commit_group;" ::: "memory")
#define CP_WAIT(n)  asm volatile("cp.async.wait_group %0;" :: "n"(n) : "memory")
#define BARG() asm volatile("bar.sync 1, 256;" ::: "memory")
#define BARC() asm volatile("bar.sync 2, 128;" ::: "memory")
#define LDSU16(r, addr) \
    asm volatile("ld.shared.u16 %0, [%1];" : "=r"(r) : "r"(addr))
#define LDSM4(r0, r1, r2, r3, addr) \
    asm volatile("ldmatrix.sync.aligned.m8n8.x4.shared.b16 {%0,%1,%2,%3}, [%4];" \
                 : "=r"(r0), "=r"(r1), "=r"(r2), "=r"(r3) : "r"(addr))
#define LDSM2(r0, r1, addr) \
    asm volatile("ldmatrix.sync.aligned.m8n8.x2.shared.b16 {%0,%1}, [%2];" \
                 : "=r"(r0), "=r"(r1) : "r"(addr))
#define MMA16816(d, a0, a1, a2, a3, b0, b1) \
    asm volatile("mma.sync.aligned.m16n8k16.row.col.f32.f16.f16.f32 " \
                 "{%0,%1,%2,%3}, {%4,%5,%6,%7}, {%8,%9}, {%0,%1,%2,%3};" \
                 : "+f"((d)[0]), "+f"((d)[1]), "+f"((d)[2]), "+f"((d)[3]) \
                 : "r"(a0), "r"(a1), "r"(a2), "r"(a3), "r"(b0), "r"(b1))

__device__ __forceinline__ uint32_t u8x2_to_h2(uint32_t w) {
    uint32_t r;
    asm("prmt.b32 %0, %1, 0, 0x4140;" : "=r"(r) : "r"(w));
    r |= 0x64006400u;
    asm("sub.rn.f16x2 %0, %0, %1;" : "+r"(r) : "r"(0x64006400u));
    return r;
}

// ---------------- setup ----------------
__global__ void k_feat(const float* __restrict__ ref, const float* __restrict__ kstd) {
    if (blockIdx.x == 0 && threadIdx.x == 0) {
        float w[KW]; float s = 0.f;
        for (int t = 0; t < KW; ++t) {
            float d = (float)t - (float)RAD;
            w[t] = expf(-(d * d) / 72.0f); s += w[t];
        }
        float inv = 1.0f / s;
        for (int t = 0; t < KW; ++t) g_g1d[t] = w[t] * inv;
    }
    int i = blockIdx.x * blockDim.x + threadIdx.x;
    if (i >= NPIX) return;
    int y = i / HW, x = i % HW;
    float f0 = (float)y / kstd[0];
    float f1 = (float)x / kstd[1];
    float f2 = ref[0 * NPIX + i] / kstd[2];
    float f3 = ref[1 * NPIX + i] / kstd[3];
    float f4 = ref[2 * NPIX + i] / kstd[4];
    g_feat[0][i] = f0; g_feat[1][i] = f1; g_feat[2][i] = f2;
    g_feat[3][i] = f3; g_feat[4][i] = f4;
    g_nhalf[i] = -0.5f * (f0 * f0 + f1 * f1 + f2 * f2 + f3 * f3 + f4 * f4);
}

// symmetric K: upper-triangle 128x128 tiles (unchanged from R13)
__global__ void __launch_bounds__(256) k_K() {
    const int a = blockIdx.y, b = blockIdx.x;
    if (a > b) return;
    __shared__ float fA[5][128], fB[5][128], nA[128], nB[128];
    __shared__ unsigned char sT[128 * 132];
    __shared__ float redR[16][128], redC[16][128];
    const int tid = threadIdx.x;
    const int tr = tid >> 4, tc = tid & 15;

    if (tid < 128) {
#pragma unroll
        for (int d = 0; d < 5; ++d) {
            fA[d][tid] = g_feat[d][a * 128 + tid];
            fB[d][tid] = g_feat[d][b * 128 + tid];
        }
        nA[tid] = g_nhalf[a * 128 + tid];
        nB[tid] = g_nhalf[b * 128 + tid];
    }
    __syncthreads();

    float rf[5][8], nri[8];
#pragma unroll
    for (int i = 0; i < 8; ++i) {
#pragma unroll
        for (int d = 0; d < 5; ++d) rf[d][i] = fA[d][tr * 8 + i];
        nri[i] = nA[tr * 8 + i];
    }
    float rs[8];
#pragma unroll
    for (int i = 0; i < 8; ++i) rs[i] = 0.f;

#pragma unroll
    for (int jj = 0; jj < 8; ++jj) {
        const int c = tc * 8 + jj;
        const float c0 = fB[0][c], c1 = fB[1][c], c2 = fB[2][c],
                    c3 = fB[3][c], c4 = fB[4][c];
        const float ncj = nB[c];
        float cs = 0.f;
#pragma unroll
        for (int i = 0; i < 8; ++i) {
            float dot = nri[i] + ncj;
            dot = fmaf(rf[0][i], c0, dot);
            dot = fmaf(rf[1][i], c1, dot);
            dot = fmaf(rf[2][i], c2, dot);
            dot = fmaf(rf[3][i], c3, dot);
            dot = fmaf(rf[4][i], c4, dot);
            float v = __expf(dot);
            rs[i] += v;
            cs += v;
            sT[(tr * 8 + i) * 132 + c] = (unsigned char)__float2uint_rn(v * 255.0f);
        }
        redC[tr][c] = cs;
    }
#pragma unroll
    for (int i = 0; i < 8; ++i) redR[tc][tr * 8 + i] = rs[i];
    __syncthreads();

    if (tid < 128) {
        float sR = 0.f, sC = 0.f;
#pragma unroll
        for (int k = 0; k < 16; ++k) { sR += redR[k][tid]; sC += redC[k][tid]; }
        g_rowpart[(a * 128 + tid) * RP + b] = sR;
        if (a != b) g_rowpart[(b * 128 + tid) * RP + a] = sC;
    }

    for (int wid = tid; wid < 4096; wid += 256) {
        const int r = wid >> 5, wc = wid & 31;
        uint32_t v = *(const uint32_t*)(sT + r * 132 + wc * 4);
        *(uint32_t*)(g_Ku + (size_t)(a * 128 + r) * NPIX + b * 128 + wc * 4) = v;
    }
    if (a != b) {
        for (int wid = tid; wid < 4096; wid += 256) {
            const int c = wid >> 5, wr = wid & 31;
            uint32_t b0 = sT[(wr * 4 + 0) * 132 + c];
            uint32_t b1 = sT[(wr * 4 + 1) * 132 + c];
            uint32_t b2 = sT[(wr * 4 + 2) * 132 + c];
            uint32_t b3 = sT[(wr * 4 + 3) * 132 + c];
            uint32_t v = b0 | (b1 << 8) | (b2 << 16) | (b3 << 24);
            *(uint32_t*)(g_Ku + (size_t)(b * 128 + c) * NPIX + a * 128 + wr * 4) = v;
        }
    }
}

__global__ void k_init(const float* __restrict__ unary) {
    int i = blockIdx.x * blockDim.x + threadIdx.x;
    if (i >= NPIX) return;
    if (i == 0) g_cnt = 0;
    if (i < GTILES) g_tick[i] = 0;
    float s = 0.f;
    const float* p = g_rowpart + i * RP;
#pragma unroll
    for (int bq = 0; bq < RP; ++bq) s += p[bq];
    float ri = 1.0f / (sqrtf(s) + 1e-8f);
    g_rowinv[i] = ri;

    float L[NCH];
    float m = -1e30f;
#pragma unroll
    for (int c = 0; c < NCH; ++c) {
        float u = unary[c * NPIX + i];
        u = fminf(fmaxf(u, 1e-5f), 1.0f);
        float lu = logf(u);
        g_U[c * NPIX + i] = lu;
        L[c] = lu;
        m = fmaxf(m, lu);
    }
    float se = 0.f;
#pragma unroll
    for (int c = 0; c < NCH; ++c) { L[c] = __expf(L[c] - m); se += L[c]; }
    float inv = 1.0f / se;
#pragma unroll
    for (int c = 0; c < NCH; ++c) {
        float q = L[c] * inv;
        g_q[c * NPIX + i] = q;
        g_qh0[c * NPIX + i] = __float2half_rn(q * ri);
    }
#pragma unroll
    for (int c = NCH; c < 32; ++c) g_qh0[c * NPIX + i] = __float2half_rn(0.f);
    if (true) {
#pragma unroll
        for (int c = NCH; c < 32; ++c) g_qh1[c * NPIX + i] = __float2half_rn(0.f);
    }
}

// ---------------- fused: GEMM (warps 0-7) + conv (warps 8-11) + update ----------------
__global__ void __launch_bounds__(384, 1) k_fused(float* __restrict__ out, int it) {
    extern __shared__ char dynRaw[];
    __shared__ float sImg[HALO * HW];
    __shared__ float sTmp[SROWS * TROW];
    __shared__ float sWc[KW];
    __shared__ int sLast;

    const uint32_t dynb = (s2u(dynRaw) + 1023u) & ~1023u;
    const int tid = threadIdx.x;
    const int m0 = blockIdx.x * 256;
    const int bid = blockIdx.y * GTILES + blockIdx.x;
    const int p = it & 1;
    const __half* qhR = p ? g_qh1 : g_qh0;
    __half* qhW = p ? g_qh0 : g_qh1;

    if (tid < 256) {
        // ================= GEMM warps =================
        const int w = tid >> 5, lid = tid & 31;
        const int zbase = blockIdx.y * KSLICE;
        const unsigned char* Abase = g_Ku + (size_t)m0 * NPIX + zbase;
        const __half* Bbase = qhR + zbase;

        auto load_chunk = [&](int ci) {
            const uint32_t stage = dynb + (uint32_t)(ci % NSTAGE) * STAGE_BYTES;
            const int koff = ci * CHUNK;
#pragma unroll
            for (int u = tid; u < 2560; u += 256) {
                uint32_t dst; const void* src;
                if (u < 2048) {
                    int r = u >> 3, t = u & 7;
                    src = Abase + (size_t)r * NPIX + koff + t * 16;
                    dst = stage + (uint32_t)(r * A_STRIDE + t * 16);
                } else {
                    int v = u - 2048;
                    int pl = v >> 8, cc = (v >> 3) & 31, t = v & 7;
                    src = Bbase + (size_t)cc * NPIX + koff + pl * 64 + t * 8;
                    dst = stage + A_PANEL + (uint32_t)pl * B_PANEL
                        + SWZ((uint32_t)(cc * 128 + t * 16));
                }
                CP16(dst, src);
            }
            CP_COMMIT();
        };

        float acc[2][3][4];
#pragma unroll
        for (int f = 0; f < 2; ++f)
#pragma unroll
            for (int g = 0; g < 3; ++g)
#pragma unroll
                for (int k = 0; k < 4; ++k) acc[f][g][k] = 0.f;

        for (int i = 0; i < NSTAGE - 1; ++i) load_chunk(i);

        const uint32_t aBase0 = (uint32_t)((w * 32 + (lid >> 2)) * A_STRIDE + (lid & 3) * 2);
        const uint32_t aBase1 = aBase0 + 16 * A_STRIDE;
        const uint32_t bRowOff01 = (uint32_t)(((lid & 7) + ((lid >> 4) << 3)) * 128) + (((lid >> 3) & 1) << 4);
        const uint32_t bRowOff2 = (uint32_t)((16 + (lid & 7)) * 128) + (((lid >> 3) & 1) << 4);

        for (int i = 0; i < NCHUNK; ++i) {
            if (i + NSTAGE - 1 < NCHUNK) CP_WAIT(NSTAGE - 2); else CP_WAIT(0);
            BARG();
            if (i + NSTAGE - 1 < NCHUNK) load_chunk(i + NSTAGE - 1);

            const uint32_t stage = dynb + (uint32_t)(i % NSTAGE) * STAGE_BYTES;
#pragma unroll
            for (int pl = 0; pl < 2; ++pl) {
                const uint32_t aOff = stage + (uint32_t)pl * 64;
                const uint32_t bufB = stage + A_PANEL + (uint32_t)pl * B_PANEL;
#pragma unroll
                for (int ks = 0; ks < 4; ++ks) {
                    const uint32_t kb = (uint32_t)ks * 32;
                    uint32_t b00, b01, b10, b11, b20, b21;
                    LDSM4(b00, b01, b10, b11, bufB + SWZ(bRowOff01 + kb));
                    LDSM2(b20, b21, bufB + SWZ(bRowOff2 + kb));

                    const uint32_t ad0 = aOff + aBase0 + (uint32_t)ks * 16;
                    const uint32_t ad1 = aOff + aBase1 + (uint32_t)ks * 16;
                    uint32_t w0, w1, w2, w3, w4, w5, w6, w7;
                    LDSU16(w0, ad0);
                    LDSU16(w1, ad0 + 8 * A_STRIDE);
                    LDSU16(w2, ad0 + 8);
                    LDSU16(w3, ad0 + 8 * A_STRIDE + 8);
                    LDSU16(w4, ad1);
                    LDSU16(w5, ad1 + 8 * A_STRIDE);
                    LDSU16(w6, ad1 + 8);
                    LDSU16(w7, ad1 + 8 * A_STRIDE + 8);
                    const uint32_t a00 = u8x2_to_h2(w0);
                    const uint32_t a01 = u8x2_to_h2(w1);
                    const uint32_t a02 = u8x2_to_h2(w2);
                    const uint32_t a03 = u8x2_to_h2(w3);
                    const uint32_t a10 = u8x2_to_h2(w4);
                    const uint32_t a11 = u8x2_to_h2(w5);
                    const uint32_t a12 = u8x2_to_h2(w6);
                    const uint32_t a13 = u8x2_to_h2(w7);

                    MMA16816(acc[0][0], a00, a01, a02, a03, b00, b01);
                    MMA16816(acc[0][1], a00, a01, a02, a03, b10, b11);
                    MMA16816(acc[0][2], a00, a01, a02, a03, b20, b21);
                    MMA16816(acc[1][0], a10, a11, a12, a13, b00, b01);
                    MMA16816(acc[1][1], a10, a11, a12, a13, b10, b11);
                    MMA16816(acc[1][2], a10, a11, a12, a13, b20, b21);
                }
            }
        }

        const int c0 = (lid & 3) * 2;
        float* pp = g_part + (size_t)blockIdx.y * (NCH * NPIX);
#pragma unroll
        for (int f = 0; f < 2; ++f) {
            const int row0 = m0 + w * 32 + f * 16 + (lid >> 2);
#pragma unroll
            for (int g = 0; g < 3; ++g) {
#pragma unroll
                for (int k = 0; k < 4; ++k) {
                    int c = g * 8 + c0 + (k & 1);
                    int row = row0 + ((k >> 1) << 3);
                    if (c < NCH) pp[c * NPIX + row] = acc[f][g][k];
                }
            }
        }
        __threadfence();
    } else if (bid < NCONV) {
        // ================= conv warps: one (channel, strip) unit =================
        const int ctid = tid - 256;
        const int c = bid / STRIPS, strip = bid % STRIPS;
        const int y0 = strip * SROWS, rowLo = y0 - RAD;

        if (ctid < KW) sWc[ctid] = g_g1d[ctid];
        const float* src = g_q + c * NPIX;
        for (int px = ctid; px < HALO * HW; px += 128) {
            int r = px / HW, x = px - r * HW;
            int gr = rowLo + r;
            sImg[px] = (gr >= 0 && gr < HW) ? src[gr * HW + x] : 0.f;
        }
        for (int px = ctid; px < SROWS * TROW; px += 128) sTmp[px] = 0.f;
        BARC();

        float a[12];
#pragma unroll
        for (int j = 0; j < 12; ++j) a[j] = 0.f;
#pragma unroll
        for (int t = 0; t < KW; ++t) {
            const float wv = sWc[t];
            const int o = t * HW + ctid;
#pragma unroll
            for (int j = 0; j < 12; ++j)
                a[j] = fmaf(wv, sImg[o + 128 * j], a[j]);
        }
#pragma unroll
        for (int j = 0; j < 12; ++j) {
            int px = ctid + 128 * j;
            int y = px / HW, x = px - y * HW;
            sTmp[y * TROW + RAD + x] = a[j];
        }
        BARC();

        int bix[12];
#pragma unroll
        for (int j = 0; j < 12; ++j) {
            int px = ctid + 128 * j;
            int y = px / HW, x = px - y * HW;
            bix[j] = y * TROW + x;
            a[j] = 0.f;
        }
#pragma unroll
        for (int t = 0; t < KW; ++t) {
            const float wv = sWc[t];
#pragma unroll
            for (int j = 0; j < 12; ++j)
                a[j] = fmaf(wv, sTmp[bix[j] + t], a[j]);
        }
        float* dst = g_qsf + c * NPIX + y0 * HW;
#pragma unroll
        for (int j = 0; j < 12; ++j) dst[ctid + 128 * j] = a[j];
        __threadfence();
        BARC();
        if (ctid == 0) atomicAdd(&g_cnt, 1);
    }

    // ================= convergence: ticket + fused softmax update =================
    __syncthreads();
    if (tid == 0) {
        int old = atomicAdd(&g_tick[blockIdx.x], 1);
        sLast = (old == KSPLIT - 1) ? 1 : 0;
    }
    __syncthreads();
    if (sLast) {
        if (tid == 0) {
            const int need = NCONV * (it + 1);
            while (atomicAdd(&g_cnt, 0) < need) { }
        }
        __syncthreads();
        __threadfence();
        if (tid < 256) {
            const int i = m0 + tid;
            const float ri = g_rowinv[i];
            float L[NCH];
            float m = -1e30f;
#pragma unroll
            for (int c = 0; c < NCH; ++c) {
                float s = g_part[c * NPIX + i] + g_part[(NCH + c) * NPIX + i]
                        + g_part[(2 * NCH + c) * NPIX + i] + g_part[(3 * NCH + c) * NPIX + i];
                float l = g_U[c * NPIX + i] + (s * ri) * BSCALE + 2.0f * g_qsf[c * NPIX + i];
                L[c] = l;
                m = fmaxf(m, l);
            }
            float se = 0.f;
#pragma unroll
            for (int c = 0; c < NCH; ++c) { L[c] = __expf(L[c] - m); se += L[c]; }
            float inv = 1.0f / se;
#pragma unroll
            for (int c = 0; c < NCH; ++c) {
                float q = L[c] * inv;
                g_q[c * NPIX + i] = q;
                qhW[c * NPIX + i] = __float2half_rn(q * ri);
                if (it == 4) out[c * NPIX + i] = q;
            }
        }
        if (tid == 0) g_tick[blockIdx.x] = 0;
    }
}

// ---------------- launch ----------------
extern "C" void kernel_launch(void* const* d_in, const int* in_sizes, int n_in,
                              void* d_out, int out_size) {
    const float* unary = nullptr;
    const float* ref = nullptr;
    const float* kstd = nullptr;
    for (int i = 0; i < n_in; ++i) {
        if (in_sizes[i] == NCH * NPIX) unary = (const float*)d_in[i];
        else if (in_sizes[i] == 3 * NPIX) ref = (const float*)d_in[i];
        else if (in_sizes[i] == 5) kstd = (const float*)d_in[i];
    }

    cudaFuncSetAttribute(k_fused, cudaFuncAttributeMaxDynamicSharedMemorySize, DYN_SMEM);

    k_feat<<<(NPIX + 255) / 256, 256>>>(ref, kstd);
    k_K<<<dim3(RP, RP), 256>>>();
    k_init<<<(NPIX + 255) / 256, 256>>>(unary);

    for (int it = 0; it < 5; ++it)
        k_fused<<<dim3(GTILES, KSPLIT), 384, DYN_SMEM>>>((float*)d_out, it);
}